// round 13
// baseline (speedup 1.0000x reference)
#include <cuda_runtime.h>
#include <cuda_bf16.h>
#include <math.h>
#include <stdint.h>

#define Bb 4
#define Nn 1024
#define Dd 1024
#define Tt 4
#define Ee 4
#define Mm 4096

// ---------------- PTX helpers (sm_80+ portable) ----------------
__device__ __forceinline__ uint32_t smem_u32(const void* p) {
  uint32_t a;
  asm("{ .reg .u64 t; cvta.to.shared.u64 t, %1; cvt.u32.u64 %0, t; }" : "=r"(a) : "l"(p));
  return a;
}
#define CPA16(d, s) asm volatile("cp.async.cg.shared.global [%0], [%1], 16;" ::"r"(d), "l"(s))
#define CP_COMMIT() asm volatile("cp.async.commit_group;" ::: "memory")
#define CP_WAIT0() asm volatile("cp.async.wait_group 0;" ::: "memory")
#define LDSM4(r, a)                                                          \
  asm volatile("ldmatrix.sync.aligned.m8n8.x4.shared.b16 {%0,%1,%2,%3}, [%4];" \
               : "=r"((r)[0]), "=r"((r)[1]), "=r"((r)[2]), "=r"((r)[3])     \
               : "r"(a))
#define MMA16816(c, a, b)                                                      \
  asm volatile(                                                                \
      "mma.sync.aligned.m16n8k16.row.col.f32.bf16.bf16.f32 "                   \
      "{%0,%1,%2,%3},{%4,%5,%6,%7},{%8,%9},{%0,%1,%2,%3};"                     \
      : "+f"((c)[0]), "+f"((c)[1]), "+f"((c)[2]), "+f"((c)[3])                 \
      : "r"((a)[0]), "r"((a)[1]), "r"((a)[2]), "r"((a)[3]), "r"((b)[0]),       \
        "r"((b)[1]))

__device__ __forceinline__ void split2(float x, __nv_bfloat16& h, __nv_bfloat16& l) {
  h = __float2bfloat16(x);
  l = __float2bfloat16(x - __bfloat162float(h));
}

// ---------------- scratch ----------------
#define AL __align__(256)
__device__ AL float g_plf32[Mm * Dd], g_vE[Mm * Dd];
__device__ AL float g_qs[Ee * Mm], g_ksE[Ee * Mm], g_qbase[Bb * Dd], g_cmd[Bb * Dd],
    g_pk[Tt * Bb * Dd], g_pv[Tt * Bb * Dd], g_ic[3 * Dd];
__device__ AL float g_wq1[Ee * 3 * Dd], g_wk2[Tt * 16 * 3 * Dd], g_qb[Ee], g_kb[Tt * 16];
__device__ AL __nv_bfloat16 g_ents_h[Mm * Dd], g_ents_l[Mm * Dd], g_xc_h[Mm * Dd],
    g_xc_l[Mm * Dd], g_plpc_h[Mm * Dd], g_plpc_l[Mm * Dd], g_msg_h[Mm * Dd], g_msg_l[Mm * Dd],
    g_xctx_h[Mm * Dd], g_xctx_l[Mm * Dd];
__device__ AL __nv_bfloat16 g_prob_h[Mm * Nn], g_prob_l[Mm * Nn], g_vT_h[Bb * Dd * Nn],
    g_vT_l[Bb * Dd * Nn];
__device__ AL __nv_bfloat16 g_wpl_h[Dd * Dd], g_wpl_l[Dd * Dd], g_wpc_h[Dd * Dd],
    g_wpc_l[Dd * Dd];
__device__ AL __nv_bfloat16 g_wv_h[Dd * 3 * Dd], g_wv_l[Dd * 3 * Dd];
__device__ AL __nv_bfloat16 g_wmu_h[Dd * 2 * Dd], g_wmu_l[Dd * 2 * Dd], g_wcb_h[Dd * 2 * Dd],
    g_wcb_l[Dd * 2 * Dd];

// ---------------- mma.sync split-bf16 GEMM (unified epilogue) ----------------
struct GA {
  const __nv_bfloat16 *Ah[3], *Al[3], *Bh[3], *Bl[3];
  long lda[3], ldb[3];
  int nseg;
  long bstrideB;
  float* C;
  __nv_bfloat16 *Oh, *Ol;    // split output, row-major
  __nv_bfloat16 *OTh, *OTl;  // split output, transposed per-batch [b][n][m&1023]
  const float* bias;
  const float* scale;
  const float* Cadd;
  const float* Cmul;
  const float* rowv;
  const float* colv;
  const float* rowmul;
};

#define KPAD 40
#define MATB 10240u
#define STAGEB 40960u
#define NSTAGE 2
#define SMEM_DYN (NSTAGE * STAGEB)  // 80 KB -> 2 CTAs/SM (also reused as 128x132 f32 epi buf)

__device__ __forceinline__ void load_chunk(const GA& ga, int c, uint32_t sb, int bm, int bn,
                                           int bb, int tid) {
  const int seg = c >> 5, k0 = (c & 31) * 32;
  const uint32_t st = sb + (uint32_t)(c & (NSTAGE - 1)) * STAGEB;
  const long lda = ga.lda[seg], ldb = ga.ldb[seg];
  const __nv_bfloat16* A0 = ga.Ah[seg] + (size_t)bm * lda + k0;
  const __nv_bfloat16* A1 = ga.Al[seg] + (size_t)bm * lda + k0;
  const size_t bo = (size_t)bn * ldb + k0 + (size_t)bb * ga.bstrideB;
  const __nv_bfloat16* B0 = ga.Bh[seg] + bo;
  const __nv_bfloat16* B1 = ga.Bl[seg] + bo;
#pragma unroll
  for (int qq = 0; qq < 8; qq++) {
    const int mat = qq >> 1;
    const int rem = ((qq & 1) << 8) + tid;
    const int row = rem >> 2, sg = rem & 3;
    const uint32_t dst = st + (uint32_t)mat * MATB + (uint32_t)(row * (KPAD * 2) + sg * 16);
    const __nv_bfloat16* src;
    if (mat == 0) src = A0 + (size_t)row * lda + sg * 8;
    else if (mat == 1) src = A1 + (size_t)row * lda + sg * 8;
    else if (mat == 2) src = B0 + (size_t)row * ldb + sg * 8;
    else src = B1 + (size_t)row * ldb + sg * 8;
    CPA16(dst, src);
  }
  CP_COMMIT();
}

__global__ __launch_bounds__(256, 2) void gemm_mma(GA ga) {
  extern __shared__ __align__(16) char smem[];
  const uint32_t sb = smem_u32(smem);
  const int tid = threadIdx.x, lane = tid & 31, wid = tid >> 5;
  const int wm = wid & 1, wn = wid >> 1;
  const int bm = blockIdx.y * 128, bn = blockIdx.x * 128, bb = blockIdx.y >> 3;

  float acc[4][4][4];
#pragma unroll
  for (int i = 0; i < 4; i++)
#pragma unroll
    for (int j = 0; j < 4; j++)
#pragma unroll
      for (int t = 0; t < 4; t++) acc[i][j][t] = 0.f;

  const int nch = ga.nseg * 32;
  load_chunk(ga, 0, sb, bm, bn, bb, tid);

  const int arow = wm * 64 + (lane & 15);
  const int acol = (lane >> 4) << 3;
  const int brow = wn * 32 + ((lane >> 4) << 3) + (lane & 7);
  const int bcol = ((lane >> 3) & 1) << 3;

  for (int i = 0; i < nch; i++) {
    CP_WAIT0();
    __syncthreads();
    if (i + 1 < nch) load_chunk(ga, i + 1, sb, bm, bn, bb, tid);

    const uint32_t st = sb + (uint32_t)(i & (NSTAGE - 1)) * STAGEB;
#pragma unroll
    for (int kk = 0; kk < 32; kk += 16) {
      uint32_t ah[4][4], al[4][4];
#pragma unroll
      for (int mi = 0; mi < 4; mi++) {
        const uint32_t addr = st + (uint32_t)(((arow + mi * 16) * KPAD + kk + acol) << 1);
        LDSM4(ah[mi], addr);
        LDSM4(al[mi], addr + MATB);
      }
#pragma unroll
      for (int p = 0; p < 2; p++) {
        uint32_t bh[4], bl[4];
        const uint32_t addr =
            st + 2 * MATB + (uint32_t)(((brow + p * 16) * KPAD + kk + bcol) << 1);
        LDSM4(bh, addr);
        LDSM4(bl, addr + MATB);
#pragma unroll
        for (int mi = 0; mi < 4; mi++)
#pragma unroll
          for (int nj = 0; nj < 2; nj++) {
            const int ni = p * 2 + nj;
            const uint32_t* bhp = &bh[nj * 2];
            const uint32_t* blp = &bl[nj * 2];
            MMA16816(acc[mi][ni], ah[mi], bhp);
            MMA16816(acc[mi][ni], ah[mi], blp);
            MMA16816(acc[mi][ni], al[mi], bhp);
          }
      }
    }
  }

  float* tb = (float*)smem;  // 128x132 f32 transpose buffer (epilogue reuse)
  if (ga.OTh) __syncthreads();  // all warps done reading stages before overwrite

  const int m0 = bm + wm * 64, n0 = bn + wn * 32;
#pragma unroll
  for (int mi = 0; mi < 4; mi++)
#pragma unroll
    for (int ni = 0; ni < 4; ni++)
#pragma unroll
      for (int h = 0; h < 2; h++) {
        const int m = m0 + mi * 16 + h * 8 + (lane >> 2);
        const int n = n0 + ni * 8 + (lane & 3) * 2;
        float v0 = acc[mi][ni][h * 2 + 0], v1 = acc[mi][ni][h * 2 + 1];
        const size_t off = (size_t)m * Dd + n;
        if (ga.Cadd) {
          const float2 c = *(const float2*)(ga.Cadd + off);
          v0 += c.x; v1 += c.y;
        }
        if (ga.colv) {
          const float rm = ga.rowv[m];
          const float2 cv = *(const float2*)(ga.colv + n);
          v0 += rm * cv.x; v1 += rm * cv.y;
        }
        if (ga.bias) {
          const float2 bv = *(const float2*)(ga.bias + n);
          v0 += bv.x; v1 += bv.y;
        }
        if (ga.scale) {
          const float2 sc = *(const float2*)(ga.scale + (size_t)bb * Dd + n);
          v0 *= sc.x; v1 *= sc.y;
        }
        if (ga.Cmul) {
          const float2 ci = *(const float2*)(ga.Cmul + off);
          v0 *= ci.x; v1 *= ci.y;
        }
        if (ga.OTh) {
          const int lm = m - bm, ln = n - bn;
          tb[ln * 132 + lm] = v0;
          tb[(ln + 1) * 132 + lm] = v1;
        } else {
          if (ga.C) *(float2*)(ga.C + off) = make_float2(v0, v1);
          if (ga.Oh) {
            float s0 = v0, s1 = v1;
            if (ga.rowmul) {
              const float rm = ga.rowmul[m];
              s0 *= rm; s1 *= rm;
            }
            __nv_bfloat16 h0, l0, h1, l1;
            split2(s0, h0, l0);
            split2(s1, h1, l1);
            *(__nv_bfloat162*)(ga.Oh + off) = __halves2bfloat162(h0, h1);
            *(__nv_bfloat162*)(ga.Ol + off) = __halves2bfloat162(l0, l1);
          }
        }
      }

  if (ga.OTh) {
    __syncthreads();
    const int row = tid >> 1;           // local n (0..127)
    const int c0 = (tid & 1) * 64;      // local m block
    const size_t ob =
        (size_t)bb * Dd * Nn + (size_t)(bn + row) * Nn + (size_t)(bm & 1023) + c0;
    const float* tr = tb + row * 132 + c0;
#pragma unroll
    for (int c = 0; c < 64; c += 2) {
      __nv_bfloat16 h0, l0, h1, l1;
      split2(tr[c], h0, l0);
      split2(tr[c + 1], h1, l1);
      *(__nv_bfloat162*)(ga.OTh + ob + c) = __halves2bfloat162(h0, h1);
      *(__nv_bfloat162*)(ga.OTl + ob + c) = __halves2bfloat162(l0, l1);
    }
  }
}

// ---------------- aux kernels ----------------
__global__ void split_kernel(const float* __restrict__ x, __nv_bfloat16* __restrict__ hi,
                             __nv_bfloat16* __restrict__ lo) {
  size_t i = (size_t)blockIdx.x * blockDim.x + threadIdx.x;
  float4 v = ((const float4*)x)[i];
  __nv_bfloat16 h[4], l[4];
  split2(v.x, h[0], l[0]); split2(v.y, h[1], l[1]);
  split2(v.z, h[2], l[2]); split2(v.w, h[3], l[3]);
  *(__nv_bfloat162*)(hi + i * 4) = __halves2bfloat162(h[0], h[1]);
  *(__nv_bfloat162*)(hi + i * 4 + 2) = __halves2bfloat162(h[2], h[3]);
  *(__nv_bfloat162*)(lo + i * 4) = __halves2bfloat162(l[0], l[1]);
  *(__nv_bfloat162*)(lo + i * 4 + 2) = __halves2bfloat162(l[2], l[3]);
}
__global__ void xc0_kernel(const float* __restrict__ mask, const float* __restrict__ init,
                           __nv_bfloat16* __restrict__ hi, __nv_bfloat16* __restrict__ lo) {
  size_t i = (size_t)blockIdx.x * blockDim.x + threadIdx.x;
  const int m = (int)((i * 4) >> 10), n = (int)((i * 4) & 1023);
  const float mk = mask[m];
  const float4 ic = *(const float4*)(init + n);
  __nv_bfloat16 h[4], l[4];
  split2(mk * ic.x, h[0], l[0]); split2(mk * ic.y, h[1], l[1]);
  split2(mk * ic.z, h[2], l[2]); split2(mk * ic.w, h[3], l[3]);
  *(__nv_bfloat162*)(hi + i * 4) = __halves2bfloat162(h[0], h[1]);
  *(__nv_bfloat162*)(hi + i * 4 + 2) = __halves2bfloat162(h[2], h[3]);
  *(__nv_bfloat162*)(lo + i * 4) = __halves2bfloat162(l[0], l[1]);
  *(__nv_bfloat162*)(lo + i * 4 + 2) = __halves2bfloat162(l[2], l[3]);
}
__global__ void plpc0_kernel(const float* __restrict__ mask, const float* __restrict__ icpc,
                             const float* __restrict__ bpc, const float* __restrict__ pl,
                             __nv_bfloat16* __restrict__ hi, __nv_bfloat16* __restrict__ lo) {
  size_t i = (size_t)blockIdx.x * blockDim.x + threadIdx.x;
  const int m = (int)((i * 4) >> 10), n = (int)((i * 4) & 1023);
  const float mk = mask[m];
  const float4 ic = *(const float4*)(icpc + n);
  const float4 bp = *(const float4*)(bpc + n);
  const float4 p = ((const float4*)pl)[i];
  float v0 = (mk * ic.x + bp.x) * p.x;
  float v1 = (mk * ic.y + bp.y) * p.y;
  float v2 = (mk * ic.z + bp.z) * p.z;
  float v3 = (mk * ic.w + bp.w) * p.w;
  __nv_bfloat16 h[4], l[4];
  split2(v0, h[0], l[0]); split2(v1, h[1], l[1]);
  split2(v2, h[2], l[2]); split2(v3, h[3], l[3]);
  *(__nv_bfloat162*)(hi + i * 4) = __halves2bfloat162(h[0], h[1]);
  *(__nv_bfloat162*)(hi + i * 4 + 2) = __halves2bfloat162(h[2], h[3]);
  *(__nv_bfloat162*)(lo + i * 4) = __halves2bfloat162(l[0], l[1]);
  *(__nv_bfloat162*)(lo + i * 4 + 2) = __halves2bfloat162(l[2], l[3]);
}
__global__ void small_nt(const float* __restrict__ x, const float* __restrict__ w, long ldw,
                         const float* __restrict__ b, float* __restrict__ out, int K, int act) {
  const int lane = threadIdx.x & 31, wid = threadIdx.x >> 5;
  const int n = blockIdx.x * 8 + wid, r = blockIdx.y;
  const float* xr = x + (size_t)r * K;
  const float* wr = w + (size_t)n * ldw;
  float s = 0.f;
  for (int c = lane; c < K; c += 32) s = fmaf(xr[c], wr[c], s);
#pragma unroll
  for (int o = 16; o; o >>= 1) s += __shfl_down_sync(0xffffffffu, s, o);
  if (lane == 0) {
    if (b) s += b[n];
    if (act) s = s > 0.f ? s : (expf(s) - 1.f);
    out[(size_t)r * Dd + n] = s;
  }
}
__global__ void wq1_kernel(const float* __restrict__ wq, const float* __restrict__ wes,
                           float* __restrict__ wq1) {
  int j = blockIdx.x * 256 + threadIdx.x;
  float a0 = 0, a1 = 0, a2 = 0, a3 = 0;
  for (int d = 0; d < 1024; d++) {
    float w = wq[(size_t)d * 3072 + j];
    a0 = fmaf(wes[d], w, a0);
    a1 = fmaf(wes[2048 + d], w, a1);
    a2 = fmaf(wes[4096 + d], w, a2);
    a3 = fmaf(wes[6144 + d], w, a3);
  }
  wq1[j] = a0; wq1[3072 + j] = a1; wq1[6144 + j] = a2; wq1[9216 + j] = a3;
}
__global__ void wk2_kernel(const float* __restrict__ wk, const float* __restrict__ wes,
                           const float* __restrict__ pk, float* __restrict__ wk2) {
  int j = blockIdx.x * 256 + threadIdx.x;
  float acc[16];
#pragma unroll
  for (int i = 0; i < 16; i++) acc[i] = 0.f;
  for (int d = 0; d < 1024; d++) {
    float w = wk[(size_t)d * 3072 + j];
#pragma unroll
    for (int e = 0; e < 4; e++) {
      float w2w = wes[e * 2048 + 1024 + d] * w;
#pragma unroll
      for (int b = 0; b < 4; b++) acc[e * 4 + b] = fmaf(w2w, pk[b * 1024 + d], acc[e * 4 + b]);
    }
  }
#pragma unroll
  for (int i = 0; i < 16; i++) wk2[(size_t)i * 3072 + j] = acc[i];
}
__global__ void qb_kernel(const float* __restrict__ bq, const float* __restrict__ wes,
                          float* __restrict__ qb) {
  __shared__ float red[256];
  int tid = threadIdx.x;
  for (int e = 0; e < 4; e++) {
    float s = 0.f;
    for (int d = tid; d < 1024; d += 256) s = fmaf(bq[d], wes[e * 2048 + d], s);
    red[tid] = s;
    __syncthreads();
    for (int o = 128; o; o >>= 1) {
      if (tid < o) red[tid] += red[tid + o];
      __syncthreads();
    }
    if (tid == 0) qb[e] = red[0];
    __syncthreads();
  }
}
__global__ void kb_kernel(const float* __restrict__ bk, const float* __restrict__ pk,
                          const float* __restrict__ wes, float* __restrict__ kb) {
  __shared__ float red[256];
  int tid = threadIdx.x;
  int e = blockIdx.x >> 2, b = blockIdx.x & 3;
  float s = 0.f;
  for (int d = tid; d < 1024; d += 256)
    s = fmaf(bk[d] * pk[b * 1024 + d], wes[e * 2048 + 1024 + d], s);
  red[tid] = s;
  __syncthreads();
  for (int o = 128; o; o >>= 1) {
    if (tid < o) red[tid] += red[tid + o];
    __syncthreads();
  }
  if (tid == 0) kb[blockIdx.x] = red[0];
}
__global__ __launch_bounds__(256) void qsks2_tiled(
    const __nv_bfloat16* __restrict__ eh, const __nv_bfloat16* __restrict__ el,
    const __nv_bfloat16* __restrict__ xch, const __nv_bfloat16* __restrict__ xcl,
    const __nv_bfloat16* __restrict__ pph, const __nv_bfloat16* __restrict__ ppl,
    const float* __restrict__ wq1, const float* __restrict__ wk2,
    const float* __restrict__ qb, const float* __restrict__ kb, float* __restrict__ qs,
    float* __restrict__ ks) {
  __shared__ float tq[4][512], tk[4][512];
  const int m0 = blockIdx.x * 32;
  const int b = m0 >> 10;
  const int tid = threadIdx.x, row = tid >> 3, sub = tid & 7;
  const int m = m0 + row;
  float qa[4] = {0, 0, 0, 0}, ka[4] = {0, 0, 0, 0};
  for (int c0 = 0; c0 < 3072; c0 += 512) {
    for (int i = tid; i < 4 * 512; i += 256) {
      int e = i >> 9, c = i & 511;
      tq[e][c] = wq1[e * 3072 + c0 + c];
      tk[e][c] = wk2[(size_t)(e * 4 + b) * 3072 + c0 + c];
    }
    __syncthreads();
    const int sseg = c0 >> 10;
    const __nv_bfloat16 *xh, *xl;
    if (sseg == 0) { xh = eh; xl = el; }
    else if (sseg == 1) { xh = xch; xl = xcl; }
    else { xh = pph; xl = ppl; }
    const size_t base = (size_t)m * 1024 + (c0 & 1023);
#pragma unroll 8
    for (int i = 0; i < 64; i++) {
      const int c = sub + 8 * i;
      const float x = __bfloat162float(xh[base + c]) + __bfloat162float(xl[base + c]);
#pragma unroll
      for (int e = 0; e < 4; e++) {
        qa[e] = fmaf(x, tq[e][c], qa[e]);
        ka[e] = fmaf(x, tk[e][c], ka[e]);
      }
    }
    __syncthreads();
  }
#pragma unroll
  for (int e = 0; e < 4; e++) {
#pragma unroll
    for (int o = 4; o; o >>= 1) {
      qa[e] += __shfl_down_sync(0xffffffffu, qa[e], o);
      ka[e] += __shfl_down_sync(0xffffffffu, ka[e], o);
    }
  }
  if (sub == 0) {
#pragma unroll
    for (int e = 0; e < 4; e++) {
      qs[e * Mm + m] = qa[e] + qb[e];
      ks[e * Mm + m] = ka[e] + kb[e * 4 + b];
    }
  }
}
__global__ __launch_bounds__(256) void softmax_kernel(const int* __restrict__ adj,
                                                      const int* __restrict__ types_p,
                                                      const float* __restrict__ qs,
                                                      const float* __restrict__ ks,
                                                      __nv_bfloat16* __restrict__ phi,
                                                      __nv_bfloat16* __restrict__ plo) {
  const int m = blockIdx.x, b = m / Nn, tid = threadIdx.x;
  const int types = *types_p;
  __shared__ float qsr[Ee];
  __shared__ int enr[Ee];
  if (tid < Ee) {
    qsr[tid] = qs[tid * Mm + m];
    enr[tid] = (types >> (tid + 1)) & 1;
  }
  __syncthreads();
  float lv[4], mx = -INFINITY;
#pragma unroll
  for (int s = 0; s < 4; s++) {
    int j = tid + s * 256;
    int a = adj[(size_t)m * Nn + j];
    float l;
    if (a == 0)
      l = -9e15f;
    else if (!enr[a - 1])
      l = 0.f;
    else {
      float sc = qsr[a - 1] + ks[(size_t)(a - 1) * Mm + (size_t)b * Nn + j];
      l = sc > 0.f ? sc : 0.2f * sc;
    }
    lv[s] = l;
    mx = fmaxf(mx, l);
  }
  __shared__ float red[256];
  red[tid] = mx;
  __syncthreads();
  for (int o = 128; o; o >>= 1) {
    if (tid < o) red[tid] = fmaxf(red[tid], red[tid + o]);
    __syncthreads();
  }
  mx = red[0];
  __syncthreads();
  float sum = 0.f;
#pragma unroll
  for (int s = 0; s < 4; s++) {
    lv[s] = expf(lv[s] - mx);
    sum += lv[s];
  }
  red[tid] = sum;
  __syncthreads();
  for (int o = 128; o; o >>= 1) {
    if (tid < o) red[tid] += red[tid + o];
    __syncthreads();
  }
  const float inv = 1.f / red[0];
#pragma unroll
  for (int s = 0; s < 4; s++) {
    __nv_bfloat16 h, l;
    split2(lv[s] * inv, h, l);
    phi[(size_t)m * Nn + tid + s * 256] = h;
    plo[(size_t)m * Nn + tid + s * 256] = l;
  }
}

// ---------------- host ----------------
static void seg(GA& a, int s, const __nv_bfloat16* ah, const __nv_bfloat16* al, long lda,
                const __nv_bfloat16* bh, const __nv_bfloat16* bl, long ldb) {
  a.Ah[s] = ah; a.Al[s] = al; a.lda[s] = lda;
  a.Bh[s] = bh; a.Bl[s] = bl; a.ldb[s] = ldb;
}
static void clear_epi(GA& a) {
  a.C = nullptr; a.Oh = nullptr; a.Ol = nullptr; a.OTh = nullptr; a.OTl = nullptr;
  a.bias = nullptr; a.scale = nullptr; a.Cadd = nullptr; a.Cmul = nullptr;
  a.rowv = nullptr; a.colv = nullptr; a.rowmul = nullptr;
  a.bstrideB = 0;
}
static void run(const GA& a) { gemm_mma<<<dim3(8, 32), 256, SMEM_DYN>>>(a); }
#define GSYM(v, s) cudaGetSymbolAddress((void**)&v, s)

extern "C" void kernel_launch(void* const* d_in, const int* in_sizes, int n_in, void* d_out,
                              int out_size) {
  const float* ents = (const float*)d_in[0];
  const float* ent_mask = (const float*)d_in[1];
  const float* q_enc = (const float*)d_in[2];
  const int* adj = (const int*)d_in[3];
  const int* types = (const int*)d_in[4];
  const float* init_mem = (const float*)d_in[5];
  const float* w_qin = (const float*)d_in[6];
  const float* b_qin = (const float*)d_in[7];
  const float* w_qt = (const float*)d_in[8];
  const float* b_qt = (const float*)d_in[9];
  const float* w_pl = (const float*)d_in[10];
  const float* b_pl = (const float*)d_in[11];
  const float* w_pc = (const float*)d_in[12];
  const float* b_pc = (const float*)d_in[13];
  const float* w_q = (const float*)d_in[14];
  const float* b_q = (const float*)d_in[15];
  const float* w_k = (const float*)d_in[16];
  const float* b_k = (const float*)d_in[17];
  const float* w_v = (const float*)d_in[18];
  const float* b_v = (const float*)d_in[19];
  const float* w_pk = (const float*)d_in[20];
  const float* b_pk = (const float*)d_in[21];
  const float* w_pv = (const float*)d_in[22];
  const float* b_pv = (const float*)d_in[23];
  const float* wes = (const float*)d_in[24];
  const float* w_mu = (const float*)d_in[25];
  const float* b_mu = (const float*)d_in[26];
  const float* w_cb = (const float*)d_in[27];
  const float* b_cb = (const float*)d_in[28];
  float* out = (float*)d_out;

  static cudaStream_t s1 = nullptr;
  static cudaEvent_t ev0, evSide, evPl[Tt], evProb[Tt];
  if (!s1) {
    cudaStreamCreateWithFlags(&s1, cudaStreamNonBlocking);
    cudaEventCreateWithFlags(&ev0, cudaEventDisableTiming);
    cudaEventCreateWithFlags(&evSide, cudaEventDisableTiming);
    for (int t = 0; t < Tt; t++) {
      cudaEventCreateWithFlags(&evPl[t], cudaEventDisableTiming);
      cudaEventCreateWithFlags(&evProb[t], cudaEventDisableTiming);
    }
    cudaFuncSetAttribute(gemm_mma, cudaFuncAttributeMaxDynamicSharedMemorySize, SMEM_DYN);
  }

  float *plf32, *vE, *qs, *ksE, *qbase, *cmd, *pk, *pv, *ic, *wq1, *wk2, *qb, *kb;
  GSYM(plf32, g_plf32); GSYM(vE, g_vE);
  GSYM(qs, g_qs); GSYM(ksE, g_ksE); GSYM(qbase, g_qbase); GSYM(cmd, g_cmd);
  GSYM(pk, g_pk); GSYM(pv, g_pv); GSYM(ic, g_ic);
  GSYM(wq1, g_wq1); GSYM(wk2, g_wk2); GSYM(qb, g_qb); GSYM(kb, g_kb);
  __nv_bfloat16 *eh, *el, *xch, *xcl, *pph, *ppl, *mgh, *mgl, *xth, *xtl, *prh, *prl, *vth, *vtl;
  GSYM(eh, g_ents_h); GSYM(el, g_ents_l); GSYM(xch, g_xc_h); GSYM(xcl, g_xc_l);
  GSYM(pph, g_plpc_h); GSYM(ppl, g_plpc_l); GSYM(mgh, g_msg_h); GSYM(mgl, g_msg_l);
  GSYM(xth, g_xctx_h); GSYM(xtl, g_xctx_l); GSYM(prh, g_prob_h); GSYM(prl, g_prob_l);
  GSYM(vth, g_vT_h); GSYM(vtl, g_vT_l);
  __nv_bfloat16 *wplh, *wpll, *wpch, *wpcl, *wvh, *wvl, *wmuh, *wmul2, *wcbh, *wcbl;
  GSYM(wplh, g_wpl_h); GSYM(wpll, g_wpl_l); GSYM(wpch, g_wpc_h); GSYM(wpcl, g_wpc_l);
  GSYM(wvh, g_wv_h); GSYM(wvl, g_wv_l); GSYM(wmuh, g_wmu_h); GSYM(wmul2, g_wmu_l);
  GSYM(wcbh, g_wcb_h); GSYM(wcbl, g_wcb_l);

  float* ic_pc = ic;
  float* ic_v1 = ic + Dd;
  float* ic_mu = ic + 2 * Dd;

  const int DD4 = Dd * Dd / 4;
  const int EW = Mm * Dd / 4;
  GA a;
  clear_epi(a);

  dim3 gSmall(Dd / 8, Bb);
  dim3 gOne(Dd / 8, 1);

  // ---- fork side stream ----
  cudaEventRecord(ev0, 0);
  cudaStreamWaitEvent(s1, ev0, 0);

  small_nt<<<gSmall, 256, 0, s1>>>(q_enc, w_qin, Dd, b_qin, qbase, Dd, 1);
  for (int t = 0; t < Tt; t++) {
    small_nt<<<gSmall, 256, 0, s1>>>(qbase, w_qt + (size_t)t * Dd * Dd, Dd,
                                     b_qt + (size_t)t * Dd, cmd, Dd, 0);
    small_nt<<<gSmall, 256, 0, s1>>>(cmd, w_pk, Dd, b_pk, pk + (size_t)t * Bb * Dd, Dd, 0);
    small_nt<<<gSmall, 256, 0, s1>>>(cmd, w_pv, Dd, b_pv, pv + (size_t)t * Bb * Dd, Dd, 0);
    wk2_kernel<<<12, 256, 0, s1>>>(w_k, wes, pk + (size_t)t * Bb * Dd,
                                   wk2 + (size_t)t * 16 * 3 * Dd);
    kb_kernel<<<16, 256, 0, s1>>>(b_k, pk + (size_t)t * Bb * Dd, wes, kb + t * 16);
  }
  wq1_kernel<<<12, 256, 0, s1>>>(w_q, wes, wq1);
  qb_kernel<<<1, 256, 0, s1>>>(b_q, wes, qb);
  small_nt<<<gOne, 256, 0, s1>>>(init_mem, w_pc, Dd, nullptr, ic_pc, Dd, 0);
  small_nt<<<gOne, 256, 0, s1>>>(init_mem, w_v + Dd, 3 * Dd, nullptr, ic_v1, Dd, 0);
  small_nt<<<gOne, 256, 0, s1>>>(init_mem, w_mu, 2 * Dd, nullptr, ic_mu, Dd, 0);
  split_kernel<<<DD4 / 256, 256, 0, s1>>>(w_pc, wpch, wpcl);
  split_kernel<<<2 * DD4 / 256, 256, 0, s1>>>(w_mu, wmuh, wmul2);
  cudaEventRecord(evSide, s1);

  // main stream startup
  split_kernel<<<DD4 / 256, 256>>>(w_pl, wplh, wpll);
  split_kernel<<<EW / 256, 256>>>(ents, eh, el);
  split_kernel<<<3 * DD4 / 256, 256>>>(w_v, wvh, wvl);
  split_kernel<<<2 * DD4 / 256, 256>>>(w_cb, wcbh, wcbl);
  xc0_kernel<<<EW / 256, 256>>>(ent_mask, init_mem, xch, xcl);
  a.nseg = 1;
  seg(a, 0, eh, el, Dd, wplh, wpll, Dd);
  a.C = plf32; a.bias = b_pl;
  run(a);
  clear_epi(a);
  a.nseg = 1;
  seg(a, 0, eh, el, Dd, wvh, wvl, 3 * Dd);
  a.C = vE;
  run(a);
  clear_epi(a);
  a.nseg = 1;
  seg(a, 0, eh, el, Dd, wcbh, wcbl, 2 * Dd);
  a.C = out;
  run(a);
  cudaStreamWaitEvent(0, evSide, 0);

  for (int t = 0; t < Tt; t++) {
    const float* pv_t = pv + (size_t)t * Bb * Dd;
    const float* wk2_t = wk2 + (size_t)t * 16 * 3 * Dd;
    const float* kb_t = kb + t * 16;

    if (t == 0) {
      plpc0_kernel<<<EW / 256, 256>>>(ent_mask, ic_pc, b_pc, plf32, pph, ppl);
    } else {
      clear_epi(a);
      a.nseg = 1;
      seg(a, 0, xch, xcl, Dd, wpch, wpcl, Dd);
      a.Oh = pph; a.Ol = ppl; a.bias = b_pc; a.Cmul = plf32;
      run(a);
    }
    cudaEventRecord(evPl[t], 0);

    cudaStreamWaitEvent(s1, evPl[t], 0);
    qsks2_tiled<<<Mm / 32, 256, 0, s1>>>(eh, el, xch, xcl, pph, ppl, wq1, wk2_t, qb, kb_t, qs,
                                         ksE);
    softmax_kernel<<<Mm, 256, 0, s1>>>(adj, types, qs, ksE, prh, prl);
    cudaEventRecord(evProb[t], s1);

    // v GEMM writes transposed split vT directly (epilogue smem transpose)
    if (t == 0) {
      clear_epi(a);
      a.nseg = 1;
      seg(a, 0, pph, ppl, Dd, wvh + 2 * Dd, wvl + 2 * Dd, 3 * Dd);
      a.OTh = vth; a.OTl = vtl;
      a.Cadd = vE; a.rowv = ent_mask; a.colv = ic_v1; a.bias = b_v; a.scale = pv_t;
      run(a);
    } else {
      clear_epi(a);
      a.nseg = 2;
      seg(a, 0, xch, xcl, Dd, wvh + Dd, wvl + Dd, 3 * Dd);
      seg(a, 1, pph, ppl, Dd, wvh + 2 * Dd, wvl + 2 * Dd, 3 * Dd);
      a.OTh = vth; a.OTl = vtl;
      a.Cadd = vE; a.bias = b_v; a.scale = pv_t;
      run(a);
    }

    cudaStreamWaitEvent(0, evProb[t], 0);
    clear_epi(a);
    a.nseg = 1; a.bstrideB = (long)Dd * Nn;
    seg(a, 0, prh, prl, Nn, vth, vtl, Nn);
    a.Oh = mgh; a.Ol = mgl;
    run(a);

    if (t == 0) {
      clear_epi(a);
      a.nseg = 1;
      seg(a, 0, mgh, mgl, Dd, wmuh + Dd, wmul2 + Dd, 2 * Dd);
      a.rowv = ent_mask; a.colv = ic_mu; a.bias = b_mu;
      a.Oh = xch; a.Ol = xcl; a.rowmul = ent_mask;
      run(a);
    } else {
      clear_epi(a);
      a.nseg = 2;
      seg(a, 0, xch, xcl, Dd, wmuh, wmul2, 2 * Dd);
      seg(a, 1, mgh, mgl, Dd, wmuh + Dd, wmul2 + Dd, 2 * Dd);
      a.bias = b_mu;
      if (t < Tt - 1) {
        a.Oh = xch; a.Ol = xcl; a.rowmul = ent_mask;
      } else {
        a.Oh = xth; a.Ol = xtl;
      }
      run(a);
    }
  }

  clear_epi(a);
  a.nseg = 1;
  seg(a, 0, xth, xtl, Dd, wcbh + Dd, wcbl + Dd, 2 * Dd);
  a.C = out; a.Cadd = out; a.bias = b_cb;
  run(a);
}

// round 14
// speedup vs baseline: 1.2628x; 1.2628x over previous
#include <cuda_runtime.h>
#include <cuda_bf16.h>
#include <math.h>
#include <stdint.h>

#define Bb 4
#define Nn 1024
#define Dd 1024
#define Tt 4
#define Ee 4
#define Mm 4096

// ---------------- PTX helpers (sm_80+ portable) ----------------
__device__ __forceinline__ uint32_t smem_u32(const void* p) {
  uint32_t a;
  asm("{ .reg .u64 t; cvta.to.shared.u64 t, %1; cvt.u32.u64 %0, t; }" : "=r"(a) : "l"(p));
  return a;
}
#define CPA16(d, s) asm volatile("cp.async.cg.shared.global [%0], [%1], 16;" ::"r"(d), "l"(s))
#define CP_COMMIT() asm volatile("cp.async.commit_group;" ::: "memory")
#define CP_WAIT0() asm volatile("cp.async.wait_group 0;" ::: "memory")
#define LDSM4(r, a)                                                          \
  asm volatile("ldmatrix.sync.aligned.m8n8.x4.shared.b16 {%0,%1,%2,%3}, [%4];" \
               : "=r"((r)[0]), "=r"((r)[1]), "=r"((r)[2]), "=r"((r)[3])     \
               : "r"(a))
#define MMA16816(c, a, b)                                                      \
  asm volatile(                                                                \
      "mma.sync.aligned.m16n8k16.row.col.f32.bf16.bf16.f32 "                   \
      "{%0,%1,%2,%3},{%4,%5,%6,%7},{%8,%9},{%0,%1,%2,%3};"                     \
      : "+f"((c)[0]), "+f"((c)[1]), "+f"((c)[2]), "+f"((c)[3])                 \
      : "r"((a)[0]), "r"((a)[1]), "r"((a)[2]), "r"((a)[3]), "r"((b)[0]),       \
        "r"((b)[1]))

__device__ __forceinline__ void split2(float x, __nv_bfloat16& h, __nv_bfloat16& l) {
  h = __float2bfloat16(x);
  l = __float2bfloat16(x - __bfloat162float(h));
}

// ---------------- scratch ----------------
#define AL __align__(256)
__device__ AL float g_plf32[Mm * Dd], g_vE[Mm * Dd], g_v[Mm * Dd];
__device__ AL float g_qs[Ee * Mm], g_ksE[Ee * Mm], g_qbase[Bb * Dd], g_cmd[Bb * Dd],
    g_pk[Tt * Bb * Dd], g_pv[Tt * Bb * Dd], g_ic[3 * Dd];
__device__ AL float g_wq1[Ee * 3 * Dd], g_wk2[Tt * 16 * 3 * Dd], g_wk2p[4 * 16 * 3 * Dd],
    g_qb[Ee], g_kb[Tt * 16];
__device__ AL uint8_t g_adj8[Mm * Nn];
__device__ AL __nv_bfloat16 g_ents_h[Mm * Dd], g_ents_l[Mm * Dd], g_xc_h[Mm * Dd],
    g_xc_l[Mm * Dd], g_plpc_h[Mm * Dd], g_plpc_l[Mm * Dd], g_msg_h[Mm * Dd], g_msg_l[Mm * Dd],
    g_xctx_h[Mm * Dd], g_xctx_l[Mm * Dd];
__device__ AL __nv_bfloat16 g_prob_h[Mm * Nn], g_prob_l[Mm * Nn], g_vT_h[Bb * Dd * Nn],
    g_vT_l[Bb * Dd * Nn];
__device__ AL __nv_bfloat16 g_wpl_h[Dd * Dd], g_wpl_l[Dd * Dd], g_wpc_h[Dd * Dd],
    g_wpc_l[Dd * Dd];
__device__ AL __nv_bfloat16 g_wv_h[Dd * 3 * Dd], g_wv_l[Dd * 3 * Dd];
__device__ AL __nv_bfloat16 g_wmu_h[Dd * 2 * Dd], g_wmu_l[Dd * 2 * Dd], g_wcb_h[Dd * 2 * Dd],
    g_wcb_l[Dd * 2 * Dd];

// ---------------- mma.sync split-bf16 GEMM (unified epilogue) ----------------
struct GA {
  const __nv_bfloat16 *Ah[3], *Al[3], *Bh[3], *Bl[3];
  long lda[3], ldb[3];
  int nseg;
  long bstrideB;
  float* C;
  __nv_bfloat16 *Oh, *Ol;
  const float* bias;
  const float* scale;
  const float* Cadd;
  const float* Cmul;
  const float* rowv;
  const float* colv;
  const float* rowmul;
};

#define KPAD 40
#define MATB 10240u
#define STAGEB 40960u
#define NSTAGE 2
#define SMEM_DYN (NSTAGE * STAGEB)  // 80 KB -> 2 CTAs/SM

__device__ __forceinline__ void load_chunk(const GA& ga, int c, uint32_t sb, int bm, int bn,
                                           int bb, int tid) {
  const int seg = c >> 5, k0 = (c & 31) * 32;
  const uint32_t st = sb + (uint32_t)(c & (NSTAGE - 1)) * STAGEB;
  const long lda = ga.lda[seg], ldb = ga.ldb[seg];
  const __nv_bfloat16* A0 = ga.Ah[seg] + (size_t)bm * lda + k0;
  const __nv_bfloat16* A1 = ga.Al[seg] + (size_t)bm * lda + k0;
  const size_t bo = (size_t)bn * ldb + k0 + (size_t)bb * ga.bstrideB;
  const __nv_bfloat16* B0 = ga.Bh[seg] + bo;
  const __nv_bfloat16* B1 = ga.Bl[seg] + bo;
#pragma unroll
  for (int qq = 0; qq < 8; qq++) {
    const int mat = qq >> 1;
    const int rem = ((qq & 1) << 8) + tid;
    const int row = rem >> 2, sg = rem & 3;
    const uint32_t dst = st + (uint32_t)mat * MATB + (uint32_t)(row * (KPAD * 2) + sg * 16);
    const __nv_bfloat16* src;
    if (mat == 0) src = A0 + (size_t)row * lda + sg * 8;
    else if (mat == 1) src = A1 + (size_t)row * lda + sg * 8;
    else if (mat == 2) src = B0 + (size_t)row * ldb + sg * 8;
    else src = B1 + (size_t)row * ldb + sg * 8;
    CPA16(dst, src);
  }
  CP_COMMIT();
}

__global__ __launch_bounds__(256, 2) void gemm_mma(GA ga) {
  extern __shared__ __align__(16) char smem[];
  const uint32_t sb = smem_u32(smem);
  const int tid = threadIdx.x, lane = tid & 31, wid = tid >> 5;
  const int wm = wid & 1, wn = wid >> 1;
  const int bm = blockIdx.y * 128, bn = blockIdx.x * 128, bb = blockIdx.y >> 3;

  float acc[4][4][4];
#pragma unroll
  for (int i = 0; i < 4; i++)
#pragma unroll
    for (int j = 0; j < 4; j++)
#pragma unroll
      for (int t = 0; t < 4; t++) acc[i][j][t] = 0.f;

  const int nch = ga.nseg * 32;
  load_chunk(ga, 0, sb, bm, bn, bb, tid);

  const int arow = wm * 64 + (lane & 15);
  const int acol = (lane >> 4) << 3;
  const int brow = wn * 32 + ((lane >> 4) << 3) + (lane & 7);
  const int bcol = ((lane >> 3) & 1) << 3;

  for (int i = 0; i < nch; i++) {
    CP_WAIT0();
    __syncthreads();
    if (i + 1 < nch) load_chunk(ga, i + 1, sb, bm, bn, bb, tid);

    const uint32_t st = sb + (uint32_t)(i & (NSTAGE - 1)) * STAGEB;
#pragma unroll
    for (int kk = 0; kk < 32; kk += 16) {
      uint32_t ah[4][4], al[4][4];
#pragma unroll
      for (int mi = 0; mi < 4; mi++) {
        const uint32_t addr = st + (uint32_t)(((arow + mi * 16) * KPAD + kk + acol) << 1);
        LDSM4(ah[mi], addr);
        LDSM4(al[mi], addr + MATB);
      }
#pragma unroll
      for (int p = 0; p < 2; p++) {
        uint32_t bh[4], bl[4];
        const uint32_t addr =
            st + 2 * MATB + (uint32_t)(((brow + p * 16) * KPAD + kk + bcol) << 1);
        LDSM4(bh, addr);
        LDSM4(bl, addr + MATB);
#pragma unroll
        for (int mi = 0; mi < 4; mi++)
#pragma unroll
          for (int nj = 0; nj < 2; nj++) {
            const int ni = p * 2 + nj;
            const uint32_t* bhp = &bh[nj * 2];
            const uint32_t* blp = &bl[nj * 2];
            MMA16816(acc[mi][ni], ah[mi], bhp);
            MMA16816(acc[mi][ni], ah[mi], blp);
            MMA16816(acc[mi][ni], al[mi], bhp);
          }
      }
    }
  }

  const int m0 = bm + wm * 64, n0 = bn + wn * 32;
#pragma unroll
  for (int mi = 0; mi < 4; mi++)
#pragma unroll
    for (int ni = 0; ni < 4; ni++)
#pragma unroll
      for (int h = 0; h < 2; h++) {
        const int m = m0 + mi * 16 + h * 8 + (lane >> 2);
        const int n = n0 + ni * 8 + (lane & 3) * 2;
        float v0 = acc[mi][ni][h * 2 + 0], v1 = acc[mi][ni][h * 2 + 1];
        const size_t off = (size_t)m * Dd + n;
        if (ga.Cadd) {
          const float2 c = *(const float2*)(ga.Cadd + off);
          v0 += c.x; v1 += c.y;
        }
        if (ga.colv) {
          const float rm = ga.rowv[m];
          const float2 cv = *(const float2*)(ga.colv + n);
          v0 += rm * cv.x; v1 += rm * cv.y;
        }
        if (ga.bias) {
          const float2 bv = *(const float2*)(ga.bias + n);
          v0 += bv.x; v1 += bv.y;
        }
        if (ga.scale) {
          const float2 sc = *(const float2*)(ga.scale + (size_t)bb * Dd + n);
          v0 *= sc.x; v1 *= sc.y;
        }
        if (ga.Cmul) {
          const float2 ci = *(const float2*)(ga.Cmul + off);
          v0 *= ci.x; v1 *= ci.y;
        }
        if (ga.C) *(float2*)(ga.C + off) = make_float2(v0, v1);
        if (ga.Oh) {
          float s0 = v0, s1 = v1;
          if (ga.rowmul) {
            const float rm = ga.rowmul[m];
            s0 *= rm; s1 *= rm;
          }
          __nv_bfloat16 h0, l0, h1, l1;
          split2(s0, h0, l0);
          split2(s1, h1, l1);
          *(__nv_bfloat162*)(ga.Oh + off) = __halves2bfloat162(h0, h1);
          *(__nv_bfloat162*)(ga.Ol + off) = __halves2bfloat162(l0, l1);
        }
      }
}

// ---------------- aux kernels ----------------
__global__ void split_kernel(const float* __restrict__ x, __nv_bfloat16* __restrict__ hi,
                             __nv_bfloat16* __restrict__ lo) {
  size_t i = (size_t)blockIdx.x * blockDim.x + threadIdx.x;
  float4 v = ((const float4*)x)[i];
  __nv_bfloat16 h[4], l[4];
  split2(v.x, h[0], l[0]); split2(v.y, h[1], l[1]);
  split2(v.z, h[2], l[2]); split2(v.w, h[3], l[3]);
  *(__nv_bfloat162*)(hi + i * 4) = __halves2bfloat162(h[0], h[1]);
  *(__nv_bfloat162*)(hi + i * 4 + 2) = __halves2bfloat162(h[2], h[3]);
  *(__nv_bfloat162*)(lo + i * 4) = __halves2bfloat162(l[0], l[1]);
  *(__nv_bfloat162*)(lo + i * 4 + 2) = __halves2bfloat162(l[2], l[3]);
}
__global__ void xc0_kernel(const float* __restrict__ mask, const float* __restrict__ init,
                           __nv_bfloat16* __restrict__ hi, __nv_bfloat16* __restrict__ lo) {
  size_t i = (size_t)blockIdx.x * blockDim.x + threadIdx.x;
  const int m = (int)((i * 4) >> 10), n = (int)((i * 4) & 1023);
  const float mk = mask[m];
  const float4 ic = *(const float4*)(init + n);
  __nv_bfloat16 h[4], l[4];
  split2(mk * ic.x, h[0], l[0]); split2(mk * ic.y, h[1], l[1]);
  split2(mk * ic.z, h[2], l[2]); split2(mk * ic.w, h[3], l[3]);
  *(__nv_bfloat162*)(hi + i * 4) = __halves2bfloat162(h[0], h[1]);
  *(__nv_bfloat162*)(hi + i * 4 + 2) = __halves2bfloat162(h[2], h[3]);
  *(__nv_bfloat162*)(lo + i * 4) = __halves2bfloat162(l[0], l[1]);
  *(__nv_bfloat162*)(lo + i * 4 + 2) = __halves2bfloat162(l[2], l[3]);
}
__global__ void plpc0_kernel(const float* __restrict__ mask, const float* __restrict__ icpc,
                             const float* __restrict__ bpc, const float* __restrict__ pl,
                             __nv_bfloat16* __restrict__ hi, __nv_bfloat16* __restrict__ lo) {
  size_t i = (size_t)blockIdx.x * blockDim.x + threadIdx.x;
  const int m = (int)((i * 4) >> 10), n = (int)((i * 4) & 1023);
  const float mk = mask[m];
  const float4 ic = *(const float4*)(icpc + n);
  const float4 bp = *(const float4*)(bpc + n);
  const float4 p = ((const float4*)pl)[i];
  float v0 = (mk * ic.x + bp.x) * p.x;
  float v1 = (mk * ic.y + bp.y) * p.y;
  float v2 = (mk * ic.z + bp.z) * p.z;
  float v3 = (mk * ic.w + bp.w) * p.w;
  __nv_bfloat16 h[4], l[4];
  split2(v0, h[0], l[0]); split2(v1, h[1], l[1]);
  split2(v2, h[2], l[2]); split2(v3, h[3], l[3]);
  *(__nv_bfloat162*)(hi + i * 4) = __halves2bfloat162(h[0], h[1]);
  *(__nv_bfloat162*)(hi + i * 4 + 2) = __halves2bfloat162(h[2], h[3]);
  *(__nv_bfloat162*)(lo + i * 4) = __halves2bfloat162(l[0], l[1]);
  *(__nv_bfloat162*)(lo + i * 4 + 2) = __halves2bfloat162(l[2], l[3]);
}
__global__ void vT_split_kernel(const float* __restrict__ v, __nv_bfloat16* __restrict__ hi,
                                __nv_bfloat16* __restrict__ lo) {
  __shared__ float t[32][33];
  int b = blockIdx.z, j0 = blockIdx.y * 32, d0 = blockIdx.x * 32;
  int tx = threadIdx.x, ty = threadIdx.y;
  const float* vb = v + (size_t)b * Nn * Dd;
#pragma unroll
  for (int r = 0; r < 4; r++)
    t[ty + 8 * r][tx] = vb[(size_t)(j0 + ty + 8 * r) * Dd + d0 + tx];
  __syncthreads();
  size_t ob = (size_t)b * Dd * Nn;
#pragma unroll
  for (int r = 0; r < 4; r++) {
    int d = d0 + ty + 8 * r, j = j0 + tx;
    __nv_bfloat16 h, l;
    split2(t[tx][ty + 8 * r], h, l);
    hi[ob + (size_t)d * Nn + j] = h;
    lo[ob + (size_t)d * Nn + j] = l;
  }
}
__global__ void small_nt(const float* __restrict__ x, const float* __restrict__ w, long ldw,
                         const float* __restrict__ b, float* __restrict__ out, int K, int act) {
  const int lane = threadIdx.x & 31, wid = threadIdx.x >> 5;
  const int n = blockIdx.x * 8 + wid, r = blockIdx.y;
  const float* xr = x + (size_t)r * K;
  const float* wr = w + (size_t)n * ldw;
  float s = 0.f;
  for (int c = lane; c < K; c += 32) s = fmaf(xr[c], wr[c], s);
#pragma unroll
  for (int o = 16; o; o >>= 1) s += __shfl_down_sync(0xffffffffu, s, o);
  if (lane == 0) {
    if (b) s += b[n];
    if (act) s = s > 0.f ? s : (expf(s) - 1.f);
    out[(size_t)r * Dd + n] = s;
  }
}
__global__ void wq1_kernel(const float* __restrict__ wq, const float* __restrict__ wes,
                           float* __restrict__ wq1) {
  int j = blockIdx.x * 256 + threadIdx.x;
  float a0 = 0, a1 = 0, a2 = 0, a3 = 0;
  for (int d = 0; d < 1024; d++) {
    float w = wq[(size_t)d * 3072 + j];
    a0 = fmaf(wes[d], w, a0);
    a1 = fmaf(wes[2048 + d], w, a1);
    a2 = fmaf(wes[4096 + d], w, a2);
    a3 = fmaf(wes[6144 + d], w, a3);
  }
  wq1[j] = a0; wq1[3072 + j] = a1; wq1[6144 + j] = a2; wq1[9216 + j] = a3;
}
// d-chunked partials: grid (12, 4)
__global__ void wk2_part(const float* __restrict__ wk, const float* __restrict__ wes,
                         const float* __restrict__ pk, float* __restrict__ wk2p) {
  int j = blockIdx.x * 256 + threadIdx.x;
  int d0 = blockIdx.y * 256;
  float acc[16];
#pragma unroll
  for (int i = 0; i < 16; i++) acc[i] = 0.f;
  for (int d = d0; d < d0 + 256; d++) {
    float w = wk[(size_t)d * 3072 + j];
#pragma unroll
    for (int e = 0; e < 4; e++) {
      float w2w = wes[e * 2048 + 1024 + d] * w;
#pragma unroll
      for (int b = 0; b < 4; b++) acc[e * 4 + b] = fmaf(w2w, pk[b * 1024 + d], acc[e * 4 + b]);
    }
  }
#pragma unroll
  for (int i = 0; i < 16; i++)
    wk2p[((size_t)blockIdx.y * 16 + i) * 3072 + j] = acc[i];
}
__global__ void wk2_red(const float* __restrict__ wk2p, float* __restrict__ wk2) {
  int idx = blockIdx.x * 256 + threadIdx.x;  // 16*3072
  float s = 0.f;
#pragma unroll
  for (int dc = 0; dc < 4; dc++) s += wk2p[(size_t)dc * 16 * 3072 + idx];
  wk2[idx] = s;
}
__global__ void qb_kernel(const float* __restrict__ bq, const float* __restrict__ wes,
                          float* __restrict__ qb) {
  __shared__ float red[256];
  int tid = threadIdx.x;
  for (int e = 0; e < 4; e++) {
    float s = 0.f;
    for (int d = tid; d < 1024; d += 256) s = fmaf(bq[d], wes[e * 2048 + d], s);
    red[tid] = s;
    __syncthreads();
    for (int o = 128; o; o >>= 1) {
      if (tid < o) red[tid] += red[tid + o];
      __syncthreads();
    }
    if (tid == 0) qb[e] = red[0];
    __syncthreads();
  }
}
__global__ void kb_kernel(const float* __restrict__ bk, const float* __restrict__ pk,
                          const float* __restrict__ wes, float* __restrict__ kb) {
  __shared__ float red[256];
  int tid = threadIdx.x;
  int e = blockIdx.x >> 2, b = blockIdx.x & 3;
  float s = 0.f;
  for (int d = tid; d < 1024; d += 256)
    s = fmaf(bk[d] * pk[b * 1024 + d], wes[e * 2048 + 1024 + d], s);
  red[tid] = s;
  __syncthreads();
  for (int o = 128; o; o >>= 1) {
    if (tid < o) red[tid] += red[tid + o];
    __syncthreads();
  }
  if (tid == 0) kb[blockIdx.x] = red[0];
}
__global__ void adj8_kernel(const int* __restrict__ adj, uint8_t* __restrict__ adj8) {
  size_t i = (size_t)blockIdx.x * blockDim.x + threadIdx.x;
  int4 v = ((const int4*)adj)[i];
  uchar4 o;
  o.x = (uint8_t)v.x; o.y = (uint8_t)v.y; o.z = (uint8_t)v.z; o.w = (uint8_t)v.w;
  ((uchar4*)adj8)[i] = o;
}
__global__ __launch_bounds__(256) void qsks2_tiled(
    const __nv_bfloat16* __restrict__ eh, const __nv_bfloat16* __restrict__ el,
    const __nv_bfloat16* __restrict__ xch, const __nv_bfloat16* __restrict__ xcl,
    const __nv_bfloat16* __restrict__ pph, const __nv_bfloat16* __restrict__ ppl,
    const float* __restrict__ wq1, const float* __restrict__ wk2,
    const float* __restrict__ qb, const float* __restrict__ kb, float* __restrict__ qs,
    float* __restrict__ ks) {
  __shared__ float tq[4][512], tk[4][512];
  const int m0 = blockIdx.x * 32;
  const int b = m0 >> 10;
  const int tid = threadIdx.x, row = tid >> 3, sub = tid & 7;
  const int m = m0 + row;
  float qa[4] = {0, 0, 0, 0}, ka[4] = {0, 0, 0, 0};
  for (int c0 = 0; c0 < 3072; c0 += 512) {
    for (int i = tid; i < 4 * 512; i += 256) {
      int e = i >> 9, c = i & 511;
      tq[e][c] = wq1[e * 3072 + c0 + c];
      tk[e][c] = wk2[(size_t)(e * 4 + b) * 3072 + c0 + c];
    }
    __syncthreads();
    const int sseg = c0 >> 10;
    const __nv_bfloat16 *xh, *xl;
    if (sseg == 0) { xh = eh; xl = el; }
    else if (sseg == 1) { xh = xch; xl = xcl; }
    else { xh = pph; xl = ppl; }
    const size_t base = (size_t)m * 1024 + (c0 & 1023);
#pragma unroll 8
    for (int i = 0; i < 64; i++) {
      const int c = sub + 8 * i;
      const float x = __bfloat162float(xh[base + c]) + __bfloat162float(xl[base + c]);
#pragma unroll
      for (int e = 0; e < 4; e++) {
        qa[e] = fmaf(x, tq[e][c], qa[e]);
        ka[e] = fmaf(x, tk[e][c], ka[e]);
      }
    }
    __syncthreads();
  }
#pragma unroll
  for (int e = 0; e < 4; e++) {
#pragma unroll
    for (int o = 4; o; o >>= 1) {
      qa[e] += __shfl_down_sync(0xffffffffu, qa[e], o);
      ka[e] += __shfl_down_sync(0xffffffffu, ka[e], o);
    }
  }
  if (sub == 0) {
#pragma unroll
    for (int e = 0; e < 4; e++) {
      qs[e * Mm + m] = qa[e] + qb[e];
      ks[e * Mm + m] = ka[e] + kb[e * 4 + b];
    }
  }
}
__global__ __launch_bounds__(256) void softmax_kernel(const uint8_t* __restrict__ adj8,
                                                      const int* __restrict__ types_p,
                                                      const float* __restrict__ qs,
                                                      const float* __restrict__ ks,
                                                      __nv_bfloat16* __restrict__ phi,
                                                      __nv_bfloat16* __restrict__ plo) {
  const int m = blockIdx.x, b = m / Nn, tid = threadIdx.x;
  const int types = *types_p;
  __shared__ float qsr[Ee];
  __shared__ int enr[Ee];
  if (tid < Ee) {
    qsr[tid] = qs[tid * Mm + m];
    enr[tid] = (types >> (tid + 1)) & 1;
  }
  __syncthreads();
  float lv[4], mx = -INFINITY;
  const uchar4 av = ((const uchar4*)(adj8 + (size_t)m * Nn))[tid];
  const uint8_t aarr[4] = {av.x, av.y, av.z, av.w};
#pragma unroll
  for (int s = 0; s < 4; s++) {
    int j = tid * 4 + s;
    int a = aarr[s];
    float l;
    if (a == 0)
      l = -9e15f;
    else if (!enr[a - 1])
      l = 0.f;
    else {
      float sc = qsr[a - 1] + ks[(size_t)(a - 1) * Mm + (size_t)b * Nn + j];
      l = sc > 0.f ? sc : 0.2f * sc;
    }
    lv[s] = l;
    mx = fmaxf(mx, l);
  }
  __shared__ float red[256];
  red[tid] = mx;
  __syncthreads();
  for (int o = 128; o; o >>= 1) {
    if (tid < o) red[tid] = fmaxf(red[tid], red[tid + o]);
    __syncthreads();
  }
  mx = red[0];
  __syncthreads();
  float sum = 0.f;
#pragma unroll
  for (int s = 0; s < 4; s++) {
    lv[s] = expf(lv[s] - mx);
    sum += lv[s];
  }
  red[tid] = sum;
  __syncthreads();
  for (int o = 128; o; o >>= 1) {
    if (tid < o) red[tid] += red[tid + o];
    __syncthreads();
  }
  const float inv = 1.f / red[0];
  __nv_bfloat16 h[4], l[4];
#pragma unroll
  for (int s = 0; s < 4; s++) split2(lv[s] * inv, h[s], l[s]);
  *(__nv_bfloat162*)(phi + (size_t)m * Nn + tid * 4) = __halves2bfloat162(h[0], h[1]);
  *(__nv_bfloat162*)(phi + (size_t)m * Nn + tid * 4 + 2) = __halves2bfloat162(h[2], h[3]);
  *(__nv_bfloat162*)(plo + (size_t)m * Nn + tid * 4) = __halves2bfloat162(l[0], l[1]);
  *(__nv_bfloat162*)(plo + (size_t)m * Nn + tid * 4 + 2) = __halves2bfloat162(l[2], l[3]);
}

// ---------------- host ----------------
static void seg(GA& a, int s, const __nv_bfloat16* ah, const __nv_bfloat16* al, long lda,
                const __nv_bfloat16* bh, const __nv_bfloat16* bl, long ldb) {
  a.Ah[s] = ah; a.Al[s] = al; a.lda[s] = lda;
  a.Bh[s] = bh; a.Bl[s] = bl; a.ldb[s] = ldb;
}
static void clear_epi(GA& a) {
  a.C = nullptr; a.Oh = nullptr; a.Ol = nullptr;
  a.bias = nullptr; a.scale = nullptr; a.Cadd = nullptr; a.Cmul = nullptr;
  a.rowv = nullptr; a.colv = nullptr; a.rowmul = nullptr;
  a.bstrideB = 0;
}
static void run(const GA& a) { gemm_mma<<<dim3(8, 32), 256, SMEM_DYN>>>(a); }
#define GSYM(v, s) cudaGetSymbolAddress((void**)&v, s)

extern "C" void kernel_launch(void* const* d_in, const int* in_sizes, int n_in, void* d_out,
                              int out_size) {
  const float* ents = (const float*)d_in[0];
  const float* ent_mask = (const float*)d_in[1];
  const float* q_enc = (const float*)d_in[2];
  const int* adj = (const int*)d_in[3];
  const int* types = (const int*)d_in[4];
  const float* init_mem = (const float*)d_in[5];
  const float* w_qin = (const float*)d_in[6];
  const float* b_qin = (const float*)d_in[7];
  const float* w_qt = (const float*)d_in[8];
  const float* b_qt = (const float*)d_in[9];
  const float* w_pl = (const float*)d_in[10];
  const float* b_pl = (const float*)d_in[11];
  const float* w_pc = (const float*)d_in[12];
  const float* b_pc = (const float*)d_in[13];
  const float* w_q = (const float*)d_in[14];
  const float* b_q = (const float*)d_in[15];
  const float* w_k = (const float*)d_in[16];
  const float* b_k = (const float*)d_in[17];
  const float* w_v = (const float*)d_in[18];
  const float* b_v = (const float*)d_in[19];
  const float* w_pk = (const float*)d_in[20];
  const float* b_pk = (const float*)d_in[21];
  const float* w_pv = (const float*)d_in[22];
  const float* b_pv = (const float*)d_in[23];
  const float* wes = (const float*)d_in[24];
  const float* w_mu = (const float*)d_in[25];
  const float* b_mu = (const float*)d_in[26];
  const float* w_cb = (const float*)d_in[27];
  const float* b_cb = (const float*)d_in[28];
  float* out = (float*)d_out;

  static cudaStream_t s1 = nullptr;
  static cudaEvent_t ev0, evSide, evPl[Tt], evProb[Tt];
  if (!s1) {
    cudaStreamCreateWithFlags(&s1, cudaStreamNonBlocking);
    cudaEventCreateWithFlags(&ev0, cudaEventDisableTiming);
    cudaEventCreateWithFlags(&evSide, cudaEventDisableTiming);
    for (int t = 0; t < Tt; t++) {
      cudaEventCreateWithFlags(&evPl[t], cudaEventDisableTiming);
      cudaEventCreateWithFlags(&evProb[t], cudaEventDisableTiming);
    }
    cudaFuncSetAttribute(gemm_mma, cudaFuncAttributeMaxDynamicSharedMemorySize, SMEM_DYN);
  }

  float *plf32, *vE, *v, *qs, *ksE, *qbase, *cmd, *pk, *pv, *ic, *wq1, *wk2, *wk2p, *qb, *kb;
  GSYM(plf32, g_plf32); GSYM(vE, g_vE); GSYM(v, g_v);
  GSYM(qs, g_qs); GSYM(ksE, g_ksE); GSYM(qbase, g_qbase); GSYM(cmd, g_cmd);
  GSYM(pk, g_pk); GSYM(pv, g_pv); GSYM(ic, g_ic);
  GSYM(wq1, g_wq1); GSYM(wk2, g_wk2); GSYM(wk2p, g_wk2p); GSYM(qb, g_qb); GSYM(kb, g_kb);
  uint8_t* adj8;
  GSYM(adj8, g_adj8);
  __nv_bfloat16 *eh, *el, *xch, *xcl, *pph, *ppl, *mgh, *mgl, *xth, *xtl, *prh, *prl, *vth, *vtl;
  GSYM(eh, g_ents_h); GSYM(el, g_ents_l); GSYM(xch, g_xc_h); GSYM(xcl, g_xc_l);
  GSYM(pph, g_plpc_h); GSYM(ppl, g_plpc_l); GSYM(mgh, g_msg_h); GSYM(mgl, g_msg_l);
  GSYM(xth, g_xctx_h); GSYM(xtl, g_xctx_l); GSYM(prh, g_prob_h); GSYM(prl, g_prob_l);
  GSYM(vth, g_vT_h); GSYM(vtl, g_vT_l);
  __nv_bfloat16 *wplh, *wpll, *wpch, *wpcl, *wvh, *wvl, *wmuh, *wmul2, *wcbh, *wcbl;
  GSYM(wplh, g_wpl_h); GSYM(wpll, g_wpl_l); GSYM(wpch, g_wpc_h); GSYM(wpcl, g_wpc_l);
  GSYM(wvh, g_wv_h); GSYM(wvl, g_wv_l); GSYM(wmuh, g_wmu_h); GSYM(wmul2, g_wmu_l);
  GSYM(wcbh, g_wcb_h); GSYM(wcbl, g_wcb_l);

  float* ic_pc = ic;
  float* ic_v1 = ic + Dd;
  float* ic_mu = ic + 2 * Dd;

  const int DD4 = Dd * Dd / 4;
  const int EW = Mm * Dd / 4;
  GA a;
  clear_epi(a);

  dim3 gSmall(Dd / 8, Bb);
  dim3 gOne(Dd / 8, 1);

  // ---- fork side stream ----
  cudaEventRecord(ev0, 0);
  cudaStreamWaitEvent(s1, ev0, 0);

  adj8_kernel<<<Mm * Nn / 4 / 256, 256, 0, s1>>>(adj, adj8);
  small_nt<<<gSmall, 256, 0, s1>>>(q_enc, w_qin, Dd, b_qin, qbase, Dd, 1);
  for (int t = 0; t < Tt; t++) {
    small_nt<<<gSmall, 256, 0, s1>>>(qbase, w_qt + (size_t)t * Dd * Dd, Dd,
                                     b_qt + (size_t)t * Dd, cmd, Dd, 0);
    small_nt<<<gSmall, 256, 0, s1>>>(cmd, w_pk, Dd, b_pk, pk + (size_t)t * Bb * Dd, Dd, 0);
    small_nt<<<gSmall, 256, 0, s1>>>(cmd, w_pv, Dd, b_pv, pv + (size_t)t * Bb * Dd, Dd, 0);
    wk2_part<<<dim3(12, 4), 256, 0, s1>>>(w_k, wes, pk + (size_t)t * Bb * Dd, wk2p);
    wk2_red<<<192, 256, 0, s1>>>(wk2p, wk2 + (size_t)t * 16 * 3 * Dd);
    kb_kernel<<<16, 256, 0, s1>>>(b_k, pk + (size_t)t * Bb * Dd, wes, kb + t * 16);
  }
  wq1_kernel<<<12, 256, 0, s1>>>(w_q, wes, wq1);
  qb_kernel<<<1, 256, 0, s1>>>(b_q, wes, qb);
  small_nt<<<gOne, 256, 0, s1>>>(init_mem, w_pc, Dd, nullptr, ic_pc, Dd, 0);
  small_nt<<<gOne, 256, 0, s1>>>(init_mem, w_v + Dd, 3 * Dd, nullptr, ic_v1, Dd, 0);
  small_nt<<<gOne, 256, 0, s1>>>(init_mem, w_mu, 2 * Dd, nullptr, ic_mu, Dd, 0);
  split_kernel<<<DD4 / 256, 256, 0, s1>>>(w_pc, wpch, wpcl);
  split_kernel<<<2 * DD4 / 256, 256, 0, s1>>>(w_mu, wmuh, wmul2);
  cudaEventRecord(evSide, s1);

  // main stream startup
  split_kernel<<<DD4 / 256, 256>>>(w_pl, wplh, wpll);
  split_kernel<<<EW / 256, 256>>>(ents, eh, el);
  split_kernel<<<3 * DD4 / 256, 256>>>(w_v, wvh, wvl);
  split_kernel<<<2 * DD4 / 256, 256>>>(w_cb, wcbh, wcbl);
  xc0_kernel<<<EW / 256, 256>>>(ent_mask, init_mem, xch, xcl);
  a.nseg = 1;
  seg(a, 0, eh, el, Dd, wplh, wpll, Dd);
  a.C = plf32; a.bias = b_pl;
  run(a);
  clear_epi(a);
  a.nseg = 1;
  seg(a, 0, eh, el, Dd, wvh, wvl, 3 * Dd);
  a.C = vE;
  run(a);
  clear_epi(a);
  a.nseg = 1;
  seg(a, 0, eh, el, Dd, wcbh, wcbl, 2 * Dd);
  a.C = out;
  run(a);
  cudaStreamWaitEvent(0, evSide, 0);

  for (int t = 0; t < Tt; t++) {
    const float* pv_t = pv + (size_t)t * Bb * Dd;
    const float* wk2_t = wk2 + (size_t)t * 16 * 3 * Dd;
    const float* kb_t = kb + t * 16;

    if (t == 0) {
      plpc0_kernel<<<EW / 256, 256>>>(ent_mask, ic_pc, b_pc, plf32, pph, ppl);
    } else {
      clear_epi(a);
      a.nseg = 1;
      seg(a, 0, xch, xcl, Dd, wpch, wpcl, Dd);
      a.Oh = pph; a.Ol = ppl; a.bias = b_pc; a.Cmul = plf32;
      run(a);
    }
    cudaEventRecord(evPl[t], 0);

    cudaStreamWaitEvent(s1, evPl[t], 0);
    qsks2_tiled<<<Mm / 32, 256, 0, s1>>>(eh, el, xch, xcl, pph, ppl, wq1, wk2_t, qb, kb_t, qs,
                                         ksE);
    softmax_kernel<<<Mm, 256, 0, s1>>>(adj8, types, qs, ksE, prh, prl);
    cudaEventRecord(evProb[t], s1);

    if (t == 0) {
      clear_epi(a);
      a.nseg = 1;
      seg(a, 0, pph, ppl, Dd, wvh + 2 * Dd, wvl + 2 * Dd, 3 * Dd);
      a.C = v; a.Cadd = vE; a.rowv = ent_mask; a.colv = ic_v1; a.bias = b_v; a.scale = pv_t;
      run(a);
    } else {
      clear_epi(a);
      a.nseg = 2;
      seg(a, 0, xch, xcl, Dd, wvh + Dd, wvl + Dd, 3 * Dd);
      seg(a, 1, pph, ppl, Dd, wvh + 2 * Dd, wvl + 2 * Dd, 3 * Dd);
      a.C = v; a.Cadd = vE; a.bias = b_v; a.scale = pv_t;
      run(a);
    }
    vT_split_kernel<<<dim3(Dd / 32, Nn / 32, Bb), dim3(32, 8)>>>(v, vth, vtl);

    cudaStreamWaitEvent(0, evProb[t], 0);
    clear_epi(a);
    a.nseg = 1; a.bstrideB = (long)Dd * Nn;
    seg(a, 0, prh, prl, Nn, vth, vtl, Nn);
    a.Oh = mgh; a.Ol = mgl;
    run(a);

    if (t == 0) {
      clear_epi(a);
      a.nseg = 1;
      seg(a, 0, mgh, mgl, Dd, wmuh + Dd, wmul2 + Dd, 2 * Dd);
      a.rowv = ent_mask; a.colv = ic_mu; a.bias = b_mu;
      a.Oh = xch; a.Ol = xcl; a.rowmul = ent_mask;
      run(a);
    } else {
      clear_epi(a);
      a.nseg = 2;
      seg(a, 0, xch, xcl, Dd, wmuh, wmul2, 2 * Dd);
      seg(a, 1, mgh, mgl, Dd, wmuh + Dd, wmul2 + Dd, 2 * Dd);
      a.bias = b_mu;
      if (t < Tt - 1) {
        a.Oh = xch; a.Ol = xcl; a.rowmul = ent_mask;
      } else {
        a.Oh = xth; a.Ol = xtl;
      }
      run(a);
    }
  }

  clear_epi(a);
  a.nseg = 1;
  seg(a, 0, xth, xtl, Dd, wcbh + Dd, wcbl + Dd, 2 * Dd);
  a.C = out; a.Cadd = out; a.bias = b_cb;
  run(a);
}

// round 16
// speedup vs baseline: 1.2737x; 1.0087x over previous
#include <cuda_runtime.h>
#include <cuda_bf16.h>
#include <math.h>
#include <stdint.h>

#define Bb 4
#define Nn 1024
#define Dd 1024
#define Tt 4
#define Ee 4
#define Mm 4096

// ---------------- PTX helpers (sm_80+ portable) ----------------
__device__ __forceinline__ uint32_t smem_u32(const void* p) {
  uint32_t a;
  asm("{ .reg .u64 t; cvta.to.shared.u64 t, %1; cvt.u32.u64 %0, t; }" : "=r"(a) : "l"(p));
  return a;
}
#define CPA16(d, s) asm volatile("cp.async.cg.shared.global [%0], [%1], 16;" ::"r"(d), "l"(s))
#define CP_COMMIT() asm volatile("cp.async.commit_group;" ::: "memory")
#define CP_WAIT0() asm volatile("cp.async.wait_group 0;" ::: "memory")
#define LDSM4(r, a)                                                          \
  asm volatile("ldmatrix.sync.aligned.m8n8.x4.shared.b16 {%0,%1,%2,%3}, [%4];" \
               : "=r"((r)[0]), "=r"((r)[1]), "=r"((r)[2]), "=r"((r)[3])     \
               : "r"(a))
#define MMA16816(c, a, b)                                                      \
  asm volatile(                                                                \
      "mma.sync.aligned.m16n8k16.row.col.f32.bf16.bf16.f32 "                   \
      "{%0,%1,%2,%3},{%4,%5,%6,%7},{%8,%9},{%0,%1,%2,%3};"                     \
      : "+f"((c)[0]), "+f"((c)[1]), "+f"((c)[2]), "+f"((c)[3])                 \
      : "r"((a)[0]), "r"((a)[1]), "r"((a)[2]), "r"((a)[3]), "r"((b)[0]),       \
        "r"((b)[1]))

__device__ __forceinline__ void split2(float x, __nv_bfloat16& h, __nv_bfloat16& l) {
  h = __float2bfloat16(x);
  l = __float2bfloat16(x - __bfloat162float(h));
}

// ---------------- scratch ----------------
#define AL __align__(256)
__device__ AL float g_plf32[Mm * Dd], g_vE[Mm * Dd], g_v[Mm * Dd];
__device__ AL float g_qs[Ee * Mm], g_ksE[Ee * Mm], g_qbase[Bb * Dd], g_cmd[Bb * Dd],
    g_pk[Tt * Bb * Dd], g_pv[Tt * Bb * Dd], g_ic[3 * Dd];
__device__ AL float g_wq1[Ee * 3 * Dd], g_wk2[Tt * 16 * 3 * Dd], g_wk2p[4 * 16 * 3 * Dd],
    g_qb[Ee], g_kb[Tt * 16];
__device__ AL uint8_t g_adj8[Mm * Nn];
__device__ AL __nv_bfloat16 g_ents_h[Mm * Dd], g_ents_l[Mm * Dd], g_xc_h[Mm * Dd],
    g_xc_l[Mm * Dd], g_plpc_h[Mm * Dd], g_plpc_l[Mm * Dd], g_msg_h[Mm * Dd], g_msg_l[Mm * Dd],
    g_xctx_h[Mm * Dd], g_xctx_l[Mm * Dd];
__device__ AL __nv_bfloat16 g_prob_h[Mm * Nn], g_prob_l[Mm * Nn], g_vT_h[Bb * Dd * Nn],
    g_vT_l[Bb * Dd * Nn];
__device__ AL __nv_bfloat16 g_wpl_h[Dd * Dd], g_wpl_l[Dd * Dd], g_wpc_h[Dd * Dd],
    g_wpc_l[Dd * Dd];
__device__ AL __nv_bfloat16 g_wv_h[Dd * 3 * Dd], g_wv_l[Dd * 3 * Dd];
__device__ AL __nv_bfloat16 g_wmu_h[Dd * 2 * Dd], g_wmu_l[Dd * 2 * Dd], g_wcb_h[Dd * 2 * Dd],
    g_wcb_l[Dd * 2 * Dd];

// ---------------- mma.sync split-bf16 GEMM (unified epilogue) ----------------
struct GA {
  const __nv_bfloat16 *Ah[3], *Al[3], *Bh[3], *Bl[3];
  long lda[3], ldb[3];
  int nseg;
  long bstrideB;
  float* C;
  __nv_bfloat16 *Oh, *Ol;
  const float* bias;
  const float* scale;
  const float* Cadd;
  const float* Cmul;
  const float* rowv;
  const float* colv;
  const float* rowmul;
};

#define KPAD 40
#define MATB 10240u
#define STAGEB 40960u
#define NSTAGE 2
#define SMEM_DYN (NSTAGE * STAGEB)  // 80 KB -> 2 CTAs/SM

__device__ __forceinline__ void load_chunk(const GA& ga, int c, uint32_t sb, int bm, int bn,
                                           int bb, int tid) {
  const int seg = c >> 5, k0 = (c & 31) * 32;
  const uint32_t st = sb + (uint32_t)(c & (NSTAGE - 1)) * STAGEB;
  const long lda = ga.lda[seg], ldb = ga.ldb[seg];
  const __nv_bfloat16* A0 = ga.Ah[seg] + (size_t)bm * lda + k0;
  const __nv_bfloat16* A1 = ga.Al[seg] + (size_t)bm * lda + k0;
  const size_t bo = (size_t)bn * ldb + k0 + (size_t)bb * ga.bstrideB;
  const __nv_bfloat16* B0 = ga.Bh[seg] + bo;
  const __nv_bfloat16* B1 = ga.Bl[seg] + bo;
#pragma unroll
  for (int qq = 0; qq < 8; qq++) {
    const int mat = qq >> 1;
    const int rem = ((qq & 1) << 8) + tid;
    const int row = rem >> 2, sg = rem & 3;
    const uint32_t dst = st + (uint32_t)mat * MATB + (uint32_t)(row * (KPAD * 2) + sg * 16);
    const __nv_bfloat16* src;
    if (mat == 0) src = A0 + (size_t)row * lda + sg * 8;
    else if (mat == 1) src = A1 + (size_t)row * lda + sg * 8;
    else if (mat == 2) src = B0 + (size_t)row * ldb + sg * 8;
    else src = B1 + (size_t)row * ldb + sg * 8;
    CPA16(dst, src);
  }
  CP_COMMIT();
}

__global__ __launch_bounds__(256, 2) void gemm_mma(GA ga) {
  extern __shared__ __align__(16) char smem[];
  const uint32_t sb = smem_u32(smem);
  const int tid = threadIdx.x, lane = tid & 31, wid = tid >> 5;
  const int wm = wid & 1, wn = wid >> 1;
  const int bm = blockIdx.y * 128, bn = blockIdx.x * 128, bb = blockIdx.y >> 3;

  float acc[4][4][4];
#pragma unroll
  for (int i = 0; i < 4; i++)
#pragma unroll
    for (int j = 0; j < 4; j++)
#pragma unroll
      for (int t = 0; t < 4; t++) acc[i][j][t] = 0.f;

  const int nch = ga.nseg * 32;
  load_chunk(ga, 0, sb, bm, bn, bb, tid);

  const int arow = wm * 64 + (lane & 15);
  const int acol = (lane >> 4) << 3;
  const int brow = wn * 32 + ((lane >> 4) << 3) + (lane & 7);
  const int bcol = ((lane >> 3) & 1) << 3;

  for (int i = 0; i < nch; i++) {
    CP_WAIT0();
    __syncthreads();
    if (i + 1 < nch) load_chunk(ga, i + 1, sb, bm, bn, bb, tid);

    const uint32_t st = sb + (uint32_t)(i & (NSTAGE - 1)) * STAGEB;
#pragma unroll
    for (int kk = 0; kk < 32; kk += 16) {
      uint32_t ah[4][4], al[4][4];
#pragma unroll
      for (int mi = 0; mi < 4; mi++) {
        const uint32_t addr = st + (uint32_t)(((arow + mi * 16) * KPAD + kk + acol) << 1);
        LDSM4(ah[mi], addr);
        LDSM4(al[mi], addr + MATB);
      }
#pragma unroll
      for (int p = 0; p < 2; p++) {
        uint32_t bh[4], bl[4];
        const uint32_t addr =
            st + 2 * MATB + (uint32_t)(((brow + p * 16) * KPAD + kk + bcol) << 1);
        LDSM4(bh, addr);
        LDSM4(bl, addr + MATB);
#pragma unroll
        for (int mi = 0; mi < 4; mi++)
#pragma unroll
          for (int nj = 0; nj < 2; nj++) {
            const int ni = p * 2 + nj;
            const uint32_t* bhp = &bh[nj * 2];
            const uint32_t* blp = &bl[nj * 2];
            MMA16816(acc[mi][ni], ah[mi], bhp);
            MMA16816(acc[mi][ni], ah[mi], blp);
            MMA16816(acc[mi][ni], al[mi], bhp);
          }
      }
    }
  }

  const int m0 = bm + wm * 64, n0 = bn + wn * 32;
#pragma unroll
  for (int mi = 0; mi < 4; mi++)
#pragma unroll
    for (int ni = 0; ni < 4; ni++)
#pragma unroll
      for (int h = 0; h < 2; h++) {
        const int m = m0 + mi * 16 + h * 8 + (lane >> 2);
        const int n = n0 + ni * 8 + (lane & 3) * 2;
        float v0 = acc[mi][ni][h * 2 + 0], v1 = acc[mi][ni][h * 2 + 1];
        const size_t off = (size_t)m * Dd + n;
        if (ga.Cadd) {
          const float2 c = *(const float2*)(ga.Cadd + off);
          v0 += c.x; v1 += c.y;
        }
        if (ga.colv) {
          const float rm = ga.rowv[m];
          const float2 cv = *(const float2*)(ga.colv + n);
          v0 += rm * cv.x; v1 += rm * cv.y;
        }
        if (ga.bias) {
          const float2 bv = *(const float2*)(ga.bias + n);
          v0 += bv.x; v1 += bv.y;
        }
        if (ga.scale) {
          const float2 sc = *(const float2*)(ga.scale + (size_t)bb * Dd + n);
          v0 *= sc.x; v1 *= sc.y;
        }
        if (ga.Cmul) {
          const float2 ci = *(const float2*)(ga.Cmul + off);
          v0 *= ci.x; v1 *= ci.y;
        }
        if (ga.C) *(float2*)(ga.C + off) = make_float2(v0, v1);
        if (ga.Oh) {
          float s0 = v0, s1 = v1;
          if (ga.rowmul) {
            const float rm = ga.rowmul[m];
            s0 *= rm; s1 *= rm;
          }
          __nv_bfloat16 h0, l0, h1, l1;
          split2(s0, h0, l0);
          split2(s1, h1, l1);
          *(__nv_bfloat162*)(ga.Oh + off) = __halves2bfloat162(h0, h1);
          *(__nv_bfloat162*)(ga.Ol + off) = __halves2bfloat162(l0, l1);
        }
      }
}

// ---------------- aux kernels ----------------
__global__ void split_kernel(const float* __restrict__ x, __nv_bfloat16* __restrict__ hi,
                             __nv_bfloat16* __restrict__ lo) {
  size_t i = (size_t)blockIdx.x * blockDim.x + threadIdx.x;
  float4 v = ((const float4*)x)[i];
  __nv_bfloat16 h[4], l[4];
  split2(v.x, h[0], l[0]); split2(v.y, h[1], l[1]);
  split2(v.z, h[2], l[2]); split2(v.w, h[3], l[3]);
  *(__nv_bfloat162*)(hi + i * 4) = __halves2bfloat162(h[0], h[1]);
  *(__nv_bfloat162*)(hi + i * 4 + 2) = __halves2bfloat162(h[2], h[3]);
  *(__nv_bfloat162*)(lo + i * 4) = __halves2bfloat162(l[0], l[1]);
  *(__nv_bfloat162*)(lo + i * 4 + 2) = __halves2bfloat162(l[2], l[3]);
}
__global__ void xc0_kernel(const float* __restrict__ mask, const float* __restrict__ init,
                           __nv_bfloat16* __restrict__ hi, __nv_bfloat16* __restrict__ lo) {
  size_t i = (size_t)blockIdx.x * blockDim.x + threadIdx.x;
  const int m = (int)((i * 4) >> 10), n = (int)((i * 4) & 1023);
  const float mk = mask[m];
  const float4 ic = *(const float4*)(init + n);
  __nv_bfloat16 h[4], l[4];
  split2(mk * ic.x, h[0], l[0]); split2(mk * ic.y, h[1], l[1]);
  split2(mk * ic.z, h[2], l[2]); split2(mk * ic.w, h[3], l[3]);
  *(__nv_bfloat162*)(hi + i * 4) = __halves2bfloat162(h[0], h[1]);
  *(__nv_bfloat162*)(hi + i * 4 + 2) = __halves2bfloat162(h[2], h[3]);
  *(__nv_bfloat162*)(lo + i * 4) = __halves2bfloat162(l[0], l[1]);
  *(__nv_bfloat162*)(lo + i * 4 + 2) = __halves2bfloat162(l[2], l[3]);
}
__global__ void plpc0_kernel(const float* __restrict__ mask, const float* __restrict__ icpc,
                             const float* __restrict__ bpc, const float* __restrict__ pl,
                             __nv_bfloat16* __restrict__ hi, __nv_bfloat16* __restrict__ lo) {
  size_t i = (size_t)blockIdx.x * blockDim.x + threadIdx.x;
  const int m = (int)((i * 4) >> 10), n = (int)((i * 4) & 1023);
  const float mk = mask[m];
  const float4 ic = *(const float4*)(icpc + n);
  const float4 bp = *(const float4*)(bpc + n);
  const float4 p = ((const float4*)pl)[i];
  float v0 = (mk * ic.x + bp.x) * p.x;
  float v1 = (mk * ic.y + bp.y) * p.y;
  float v2 = (mk * ic.z + bp.z) * p.z;
  float v3 = (mk * ic.w + bp.w) * p.w;
  __nv_bfloat16 h[4], l[4];
  split2(v0, h[0], l[0]); split2(v1, h[1], l[1]);
  split2(v2, h[2], l[2]); split2(v3, h[3], l[3]);
  *(__nv_bfloat162*)(hi + i * 4) = __halves2bfloat162(h[0], h[1]);
  *(__nv_bfloat162*)(hi + i * 4 + 2) = __halves2bfloat162(h[2], h[3]);
  *(__nv_bfloat162*)(lo + i * 4) = __halves2bfloat162(l[0], l[1]);
  *(__nv_bfloat162*)(lo + i * 4 + 2) = __halves2bfloat162(l[2], l[3]);
}
__global__ void vT_split_kernel(const float* __restrict__ v, __nv_bfloat16* __restrict__ hi,
                                __nv_bfloat16* __restrict__ lo) {
  __shared__ float t[32][33];
  int b = blockIdx.z, j0 = blockIdx.y * 32, d0 = blockIdx.x * 32;
  int tx = threadIdx.x, ty = threadIdx.y;
  const float* vb = v + (size_t)b * Nn * Dd;
#pragma unroll
  for (int r = 0; r < 4; r++)
    t[ty + 8 * r][tx] = vb[(size_t)(j0 + ty + 8 * r) * Dd + d0 + tx];
  __syncthreads();
  size_t ob = (size_t)b * Dd * Nn;
#pragma unroll
  for (int r = 0; r < 4; r++) {
    int d = d0 + ty + 8 * r, j = j0 + tx;
    __nv_bfloat16 h, l;
    split2(t[tx][ty + 8 * r], h, l);
    hi[ob + (size_t)d * Nn + j] = h;
    lo[ob + (size_t)d * Nn + j] = l;
  }
}
__global__ void small_nt(const float* __restrict__ x, const float* __restrict__ w, long ldw,
                         const float* __restrict__ b, float* __restrict__ out, int K, int act) {
  const int lane = threadIdx.x & 31, wid = threadIdx.x >> 5;
  const int n = blockIdx.x * 8 + wid, r = blockIdx.y;
  const float* xr = x + (size_t)r * K;
  const float* wr = w + (size_t)n * ldw;
  float s = 0.f;
  for (int c = lane; c < K; c += 32) s = fmaf(xr[c], wr[c], s);
#pragma unroll
  for (int o = 16; o; o >>= 1) s += __shfl_down_sync(0xffffffffu, s, o);
  if (lane == 0) {
    if (b) s += b[n];
    if (act) s = s > 0.f ? s : (expf(s) - 1.f);
    out[(size_t)r * Dd + n] = s;
  }
}
__global__ void wq1_kernel(const float* __restrict__ wq, const float* __restrict__ wes,
                           float* __restrict__ wq1) {
  int j = blockIdx.x * 256 + threadIdx.x;
  float a0 = 0, a1 = 0, a2 = 0, a3 = 0;
  for (int d = 0; d < 1024; d++) {
    float w = wq[(size_t)d * 3072 + j];
    a0 = fmaf(wes[d], w, a0);
    a1 = fmaf(wes[2048 + d], w, a1);
    a2 = fmaf(wes[4096 + d], w, a2);
    a3 = fmaf(wes[6144 + d], w, a3);
  }
  wq1[j] = a0; wq1[3072 + j] = a1; wq1[6144 + j] = a2; wq1[9216 + j] = a3;
}
__global__ void wk2_part(const float* __restrict__ wk, const float* __restrict__ wes,
                         const float* __restrict__ pk, float* __restrict__ wk2p) {
  int j = blockIdx.x * 256 + threadIdx.x;
  int d0 = blockIdx.y * 256;
  float acc[16];
#pragma unroll
  for (int i = 0; i < 16; i++) acc[i] = 0.f;
  for (int d = d0; d < d0 + 256; d++) {
    float w = wk[(size_t)d * 3072 + j];
#pragma unroll
    for (int e = 0; e < 4; e++) {
      float w2w = wes[e * 2048 + 1024 + d] * w;
#pragma unroll
      for (int b = 0; b < 4; b++) acc[e * 4 + b] = fmaf(w2w, pk[b * 1024 + d], acc[e * 4 + b]);
    }
  }
#pragma unroll
  for (int i = 0; i < 16; i++)
    wk2p[((size_t)blockIdx.y * 16 + i) * 3072 + j] = acc[i];
}
__global__ void wk2_red(const float* __restrict__ wk2p, float* __restrict__ wk2) {
  int idx = blockIdx.x * 256 + threadIdx.x;
  float s = 0.f;
#pragma unroll
  for (int dc = 0; dc < 4; dc++) s += wk2p[(size_t)dc * 16 * 3072 + idx];
  wk2[idx] = s;
}
__global__ void qb_kernel(const float* __restrict__ bq, const float* __restrict__ wes,
                          float* __restrict__ qb) {
  __shared__ float red[256];
  int tid = threadIdx.x;
  for (int e = 0; e < 4; e++) {
    float s = 0.f;
    for (int d = tid; d < 1024; d += 256) s = fmaf(bq[d], wes[e * 2048 + d], s);
    red[tid] = s;
    __syncthreads();
    for (int o = 128; o; o >>= 1) {
      if (tid < o) red[tid] += red[tid + o];
      __syncthreads();
    }
    if (tid == 0) qb[e] = red[0];
    __syncthreads();
  }
}
__global__ void kb_kernel(const float* __restrict__ bk, const float* __restrict__ pk,
                          const float* __restrict__ wes, float* __restrict__ kb) {
  __shared__ float red[256];
  int tid = threadIdx.x;
  int e = blockIdx.x >> 2, b = blockIdx.x & 3;
  float s = 0.f;
  for (int d = tid; d < 1024; d += 256)
    s = fmaf(bk[d] * pk[b * 1024 + d], wes[e * 2048 + 1024 + d], s);
  red[tid] = s;
  __syncthreads();
  for (int o = 128; o; o >>= 1) {
    if (tid < o) red[tid] += red[tid + o];
    __syncthreads();
  }
  if (tid == 0) kb[blockIdx.x] = red[0];
}
__global__ void adj8_kernel(const int* __restrict__ adj, uint8_t* __restrict__ adj8) {
  size_t i = (size_t)blockIdx.x * blockDim.x + threadIdx.x;
  int4 v = ((const int4*)adj)[i];
  uchar4 o;
  o.x = (uint8_t)v.x; o.y = (uint8_t)v.y; o.z = (uint8_t)v.z; o.w = (uint8_t)v.w;
  ((uchar4*)adj8)[i] = o;
}
__global__ __launch_bounds__(256) void qsks2_tiled(
    const __nv_bfloat16* __restrict__ eh, const __nv_bfloat16* __restrict__ el,
    const __nv_bfloat16* __restrict__ xch, const __nv_bfloat16* __restrict__ xcl,
    const __nv_bfloat16* __restrict__ pph, const __nv_bfloat16* __restrict__ ppl,
    const float* __restrict__ wq1, const float* __restrict__ wk2,
    const float* __restrict__ qb, const float* __restrict__ kb, float* __restrict__ qs,
    float* __restrict__ ks) {
  __shared__ float tq[4][512], tk[4][512];
  const int m0 = blockIdx.x * 32;
  const int b = m0 >> 10;
  const int tid = threadIdx.x, row = tid >> 3, sub = tid & 7;
  const int m = m0 + row;
  float qa[4] = {0, 0, 0, 0}, ka[4] = {0, 0, 0, 0};
  for (int c0 = 0; c0 < 3072; c0 += 512) {
    for (int i = tid; i < 4 * 512; i += 256) {
      int e = i >> 9, c = i & 511;
      tq[e][c] = wq1[e * 3072 + c0 + c];
      tk[e][c] = wk2[(size_t)(e * 4 + b) * 3072 + c0 + c];
    }
    __syncthreads();
    const int sseg = c0 >> 10;
    const __nv_bfloat16 *xh, *xl;
    if (sseg == 0) { xh = eh; xl = el; }
    else if (sseg == 1) { xh = xch; xl = xcl; }
    else { xh = pph; xl = ppl; }
    const size_t base = (size_t)m * 1024 + (c0 & 1023);
#pragma unroll 8
    for (int i = 0; i < 64; i++) {
      const int c = sub + 8 * i;
      const float x = __bfloat162float(xh[base + c]) + __bfloat162float(xl[base + c]);
#pragma unroll
      for (int e = 0; e < 4; e++) {
        qa[e] = fmaf(x, tq[e][c], qa[e]);
        ka[e] = fmaf(x, tk[e][c], ka[e]);
      }
    }
    __syncthreads();
  }
#pragma unroll
  for (int e = 0; e < 4; e++) {
#pragma unroll
    for (int o = 4; o; o >>= 1) {
      qa[e] += __shfl_down_sync(0xffffffffu, qa[e], o);
      ka[e] += __shfl_down_sync(0xffffffffu, ka[e], o);
    }
  }
  if (sub == 0) {
#pragma unroll
    for (int e = 0; e < 4; e++) {
      qs[e * Mm + m] = qa[e] + qb[e];
      ks[e * Mm + m] = ka[e] + kb[e * 4 + b];
    }
  }
}
__global__ __launch_bounds__(256) void softmax_kernel(const uint8_t* __restrict__ adj8,
                                                      const int* __restrict__ types_p,
                                                      const float* __restrict__ qs,
                                                      const float* __restrict__ ks,
                                                      __nv_bfloat16* __restrict__ phi,
                                                      __nv_bfloat16* __restrict__ plo) {
  const int m = blockIdx.x, b = m / Nn, tid = threadIdx.x;
  const int types = *types_p;
  __shared__ float qsr[Ee];
  __shared__ int enr[Ee];
  if (tid < Ee) {
    qsr[tid] = qs[tid * Mm + m];
    enr[tid] = (types >> (tid + 1)) & 1;
  }
  __syncthreads();
  float lv[4], mx = -INFINITY;
  const uchar4 av = ((const uchar4*)(adj8 + (size_t)m * Nn))[tid];
  const uint8_t aarr[4] = {av.x, av.y, av.z, av.w};
#pragma unroll
  for (int s = 0; s < 4; s++) {
    int j = tid * 4 + s;
    int a = aarr[s];
    float l;
    if (a == 0)
      l = -9e15f;
    else if (!enr[a - 1])
      l = 0.f;
    else {
      float sc = qsr[a - 1] + ks[(size_t)(a - 1) * Mm + (size_t)b * Nn + j];
      l = sc > 0.f ? sc : 0.2f * sc;
    }
    lv[s] = l;
    mx = fmaxf(mx, l);
  }
  __shared__ float red[256];
  red[tid] = mx;
  __syncthreads();
  for (int o = 128; o; o >>= 1) {
    if (tid < o) red[tid] = fmaxf(red[tid], red[tid + o]);
    __syncthreads();
  }
  mx = red[0];
  __syncthreads();
  float sum = 0.f;
#pragma unroll
  for (int s = 0; s < 4; s++) {
    lv[s] = expf(lv[s] - mx);
    sum += lv[s];
  }
  red[tid] = sum;
  __syncthreads();
  for (int o = 128; o; o >>= 1) {
    if (tid < o) red[tid] += red[tid + o];
    __syncthreads();
  }
  const float inv = 1.f / red[0];
  __nv_bfloat16 h[4], l[4];
#pragma unroll
  for (int s = 0; s < 4; s++) split2(lv[s] * inv, h[s], l[s]);
  *(__nv_bfloat162*)(phi + (size_t)m * Nn + tid * 4) = __halves2bfloat162(h[0], h[1]);
  *(__nv_bfloat162*)(phi + (size_t)m * Nn + tid * 4 + 2) = __halves2bfloat162(h[2], h[3]);
  *(__nv_bfloat162*)(plo + (size_t)m * Nn + tid * 4) = __halves2bfloat162(l[0], l[1]);
  *(__nv_bfloat162*)(plo + (size_t)m * Nn + tid * 4 + 2) = __halves2bfloat162(l[2], l[3]);
}

// ---------------- host ----------------
static void seg(GA& a, int s, const __nv_bfloat16* ah, const __nv_bfloat16* al, long lda,
                const __nv_bfloat16* bh, const __nv_bfloat16* bl, long ldb) {
  a.Ah[s] = ah; a.Al[s] = al; a.lda[s] = lda;
  a.Bh[s] = bh; a.Bl[s] = bl; a.ldb[s] = ldb;
}
static void clear_epi(GA& a) {
  a.C = nullptr; a.Oh = nullptr; a.Ol = nullptr;
  a.bias = nullptr; a.scale = nullptr; a.Cadd = nullptr; a.Cmul = nullptr;
  a.rowv = nullptr; a.colv = nullptr; a.rowmul = nullptr;
  a.bstrideB = 0;
}
static void runS(const GA& a, cudaStream_t s) {
  gemm_mma<<<dim3(8, 32), 256, SMEM_DYN, s>>>(a);
}
#define GSYM(v, s) cudaGetSymbolAddress((void**)&v, s)

extern "C" void kernel_launch(void* const* d_in, const int* in_sizes, int n_in, void* d_out,
                              int out_size) {
  const float* ents = (const float*)d_in[0];
  const float* ent_mask = (const float*)d_in[1];
  const float* q_enc = (const float*)d_in[2];
  const int* adj = (const int*)d_in[3];
  const int* types = (const int*)d_in[4];
  const float* init_mem = (const float*)d_in[5];
  const float* w_qin = (const float*)d_in[6];
  const float* b_qin = (const float*)d_in[7];
  const float* w_qt = (const float*)d_in[8];
  const float* b_qt = (const float*)d_in[9];
  const float* w_pl = (const float*)d_in[10];
  const float* b_pl = (const float*)d_in[11];
  const float* w_pc = (const float*)d_in[12];
  const float* b_pc = (const float*)d_in[13];
  const float* w_q = (const float*)d_in[14];
  const float* b_q = (const float*)d_in[15];
  const float* w_k = (const float*)d_in[16];
  const float* b_k = (const float*)d_in[17];
  const float* w_v = (const float*)d_in[18];
  const float* b_v = (const float*)d_in[19];
  const float* w_pk = (const float*)d_in[20];
  const float* b_pk = (const float*)d_in[21];
  const float* w_pv = (const float*)d_in[22];
  const float* b_pv = (const float*)d_in[23];
  const float* wes = (const float*)d_in[24];
  const float* w_mu = (const float*)d_in[25];
  const float* b_mu = (const float*)d_in[26];
  const float* w_cb = (const float*)d_in[27];
  const float* b_cb = (const float*)d_in[28];
  float* out = (float*)d_out;

  static cudaStream_t s1 = nullptr;
  static cudaEvent_t ev0, evEnts, evIC, evVE, evOutE, evPl[Tt], evProb[Tt], evPrep[Tt];
  if (!s1) {
    cudaStreamCreateWithFlags(&s1, cudaStreamNonBlocking);
    cudaEventCreateWithFlags(&ev0, cudaEventDisableTiming);
    cudaEventCreateWithFlags(&evEnts, cudaEventDisableTiming);
    cudaEventCreateWithFlags(&evIC, cudaEventDisableTiming);
    cudaEventCreateWithFlags(&evVE, cudaEventDisableTiming);
    cudaEventCreateWithFlags(&evOutE, cudaEventDisableTiming);
    for (int t = 0; t < Tt; t++) {
      cudaEventCreateWithFlags(&evPl[t], cudaEventDisableTiming);
      cudaEventCreateWithFlags(&evProb[t], cudaEventDisableTiming);
      cudaEventCreateWithFlags(&evPrep[t], cudaEventDisableTiming);
    }
    cudaFuncSetAttribute(gemm_mma, cudaFuncAttributeMaxDynamicSharedMemorySize, SMEM_DYN);
  }

  float *plf32, *vE, *v, *qs, *ksE, *qbase, *cmd, *pk, *pv, *ic, *wq1, *wk2, *wk2p, *qb, *kb;
  GSYM(plf32, g_plf32); GSYM(vE, g_vE); GSYM(v, g_v);
  GSYM(qs, g_qs); GSYM(ksE, g_ksE); GSYM(qbase, g_qbase); GSYM(cmd, g_cmd);
  GSYM(pk, g_pk); GSYM(pv, g_pv); GSYM(ic, g_ic);
  GSYM(wq1, g_wq1); GSYM(wk2, g_wk2); GSYM(wk2p, g_wk2p); GSYM(qb, g_qb); GSYM(kb, g_kb);
  uint8_t* adj8;
  GSYM(adj8, g_adj8);
  __nv_bfloat16 *eh, *el, *xch, *xcl, *pph, *ppl, *mgh, *mgl, *xth, *xtl, *prh, *prl, *vth, *vtl;
  GSYM(eh, g_ents_h); GSYM(el, g_ents_l); GSYM(xch, g_xc_h); GSYM(xcl, g_xc_l);
  GSYM(pph, g_plpc_h); GSYM(ppl, g_plpc_l); GSYM(mgh, g_msg_h); GSYM(mgl, g_msg_l);
  GSYM(xth, g_xctx_h); GSYM(xtl, g_xctx_l); GSYM(prh, g_prob_h); GSYM(prl, g_prob_l);
  GSYM(vth, g_vT_h); GSYM(vtl, g_vT_l);
  __nv_bfloat16 *wplh, *wpll, *wpch, *wpcl, *wvh, *wvl, *wmuh, *wmul2, *wcbh, *wcbl;
  GSYM(wplh, g_wpl_h); GSYM(wpll, g_wpl_l); GSYM(wpch, g_wpc_h); GSYM(wpcl, g_wpc_l);
  GSYM(wvh, g_wv_h); GSYM(wvl, g_wv_l); GSYM(wmuh, g_wmu_h); GSYM(wmul2, g_wmu_l);
  GSYM(wcbh, g_wcb_h); GSYM(wcbl, g_wcb_l);

  float* ic_pc = ic;
  float* ic_v1 = ic + Dd;
  float* ic_mu = ic + 2 * Dd;

  const int DD4 = Dd * Dd / 4;
  const int EW = Mm * Dd / 4;
  GA a;
  clear_epi(a);

  dim3 gSmall(Dd / 8, Bb);
  dim3 gOne(Dd / 8, 1);

  // ---- phase 1: fork side stream; s1 prologue (no cross-waits yet) ----
  cudaEventRecord(ev0, 0);
  cudaStreamWaitEvent(s1, ev0, 0);
  small_nt<<<gOne, 256, 0, s1>>>(init_mem, w_pc, Dd, nullptr, ic_pc, Dd, 0);
  small_nt<<<gOne, 256, 0, s1>>>(init_mem, w_v + Dd, 3 * Dd, nullptr, ic_v1, Dd, 0);
  small_nt<<<gOne, 256, 0, s1>>>(init_mem, w_mu, 2 * Dd, nullptr, ic_mu, Dd, 0);
  cudaEventRecord(evIC, s1);
  small_nt<<<gSmall, 256, 0, s1>>>(q_enc, w_qin, Dd, b_qin, qbase, Dd, 1);
  small_nt<<<gSmall, 256, 0, s1>>>(qbase, w_qt, Dd, b_qt, cmd, Dd, 0);
  small_nt<<<gSmall, 256, 0, s1>>>(cmd, w_pk, Dd, b_pk, pk, Dd, 0);
  small_nt<<<gSmall, 256, 0, s1>>>(cmd, w_pv, Dd, b_pv, pv, Dd, 0);
  wk2_part<<<dim3(12, 4), 256, 0, s1>>>(w_k, wes, pk, wk2p);
  wk2_red<<<192, 256, 0, s1>>>(wk2p, wk2);
  kb_kernel<<<16, 256, 0, s1>>>(b_k, pk, wes, kb);
  wq1_kernel<<<12, 256, 0, s1>>>(w_q, wes, wq1);
  qb_kernel<<<1, 256, 0, s1>>>(b_q, wes, qb);
  cudaEventRecord(evPrep[0], s1);

  // ---- phase 2: main splits; record evEnts BEFORE s1 waits on it ----
  split_kernel<<<EW / 256, 256>>>(ents, eh, el);
  split_kernel<<<3 * DD4 / 256, 256>>>(w_v, wvh, wvl);
  split_kernel<<<2 * DD4 / 256, 256>>>(w_cb, wcbh, wcbl);
  cudaEventRecord(evEnts, 0);

  // ---- phase 3: s1 continues (wait is after record in program order) ----
  cudaStreamWaitEvent(s1, evEnts, 0);
  clear_epi(a);
  a.nseg = 1;
  seg(a, 0, eh, el, Dd, wvh, wvl, 3 * Dd);
  a.C = vE;
  runS(a, s1);
  cudaEventRecord(evVE, s1);
  adj8_kernel<<<Mm * Nn / 4 / 256, 256, 0, s1>>>(adj, adj8);
  split_kernel<<<DD4 / 256, 256, 0, s1>>>(w_pc, wpch, wpcl);
  split_kernel<<<2 * DD4 / 256, 256, 0, s1>>>(w_mu, wmuh, wmul2);

  // ---- phase 4: rest of main startup ----
  split_kernel<<<DD4 / 256, 256>>>(w_pl, wplh, wpll);
  xc0_kernel<<<EW / 256, 256>>>(ent_mask, init_mem, xch, xcl);
  clear_epi(a);
  a.nseg = 1;
  seg(a, 0, eh, el, Dd, wplh, wpll, Dd);
  a.C = plf32; a.bias = b_pl;
  runS(a, 0);
  cudaStreamWaitEvent(0, evIC, 0);

  for (int t = 0; t < Tt; t++) {
    const float* pv_t = pv + (size_t)t * Bb * Dd;
    const float* wk2_t = wk2 + (size_t)t * 16 * 3 * Dd;
    const float* kb_t = kb + t * 16;

    if (t == 0) {
      plpc0_kernel<<<EW / 256, 256>>>(ent_mask, ic_pc, b_pc, plf32, pph, ppl);
    } else {
      clear_epi(a);
      a.nseg = 1;
      seg(a, 0, xch, xcl, Dd, wpch, wpcl, Dd);
      a.Oh = pph; a.Ol = ppl; a.bias = b_pc; a.Cmul = plf32;
      runS(a, 0);
    }
    cudaEventRecord(evPl[t], 0);

    // side: qs/ks + softmax for this t, then outE (t=0) and prep for t+1
    cudaStreamWaitEvent(s1, evPl[t], 0);
    qsks2_tiled<<<Mm / 32, 256, 0, s1>>>(eh, el, xch, xcl, pph, ppl, wq1, wk2_t, qb, kb_t, qs,
                                         ksE);
    softmax_kernel<<<Mm, 256, 0, s1>>>(adj8, types, qs, ksE, prh, prl);
    cudaEventRecord(evProb[t], s1);
    if (t == 0) {
      clear_epi(a);
      a.nseg = 1;
      seg(a, 0, eh, el, Dd, wcbh, wcbl, 2 * Dd);
      a.C = out;
      runS(a, s1);
      cudaEventRecord(evOutE, s1);
    }
    if (t + 1 < Tt) {
      const int u = t + 1;
      small_nt<<<gSmall, 256, 0, s1>>>(qbase, w_qt + (size_t)u * Dd * Dd, Dd,
                                       b_qt + (size_t)u * Dd, cmd, Dd, 0);
      small_nt<<<gSmall, 256, 0, s1>>>(cmd, w_pk, Dd, b_pk, pk + (size_t)u * Bb * Dd, Dd, 0);
      small_nt<<<gSmall, 256, 0, s1>>>(cmd, w_pv, Dd, b_pv, pv + (size_t)u * Bb * Dd, Dd, 0);
      wk2_part<<<dim3(12, 4), 256, 0, s1>>>(w_k, wes, pk + (size_t)u * Bb * Dd, wk2p);
      wk2_red<<<192, 256, 0, s1>>>(wk2p, wk2 + (size_t)u * 16 * 3 * Dd);
      kb_kernel<<<16, 256, 0, s1>>>(b_k, pk + (size_t)u * Bb * Dd, wes, kb + u * 16);
      cudaEventRecord(evPrep[u], s1);
    }

    // main: v GEMM
    cudaStreamWaitEvent(0, evPrep[t], 0);  // pv_t ready
    if (t == 0) {
      cudaStreamWaitEvent(0, evVE, 0);  // vE ready
      clear_epi(a);
      a.nseg = 1;
      seg(a, 0, pph, ppl, Dd, wvh + 2 * Dd, wvl + 2 * Dd, 3 * Dd);
      a.C = v; a.Cadd = vE; a.rowv = ent_mask; a.colv = ic_v1; a.bias = b_v; a.scale = pv_t;
      runS(a, 0);
    } else {
      clear_epi(a);
      a.nseg = 2;
      seg(a, 0, xch, xcl, Dd, wvh + Dd, wvl + Dd, 3 * Dd);
      seg(a, 1, pph, ppl, Dd, wvh + 2 * Dd, wvl + 2 * Dd, 3 * Dd);
      a.C = v; a.Cadd = vE; a.bias = b_v; a.scale = pv_t;
      runS(a, 0);
    }
    vT_split_kernel<<<dim3(Dd / 32, Nn / 32, Bb), dim3(32, 8)>>>(v, vth, vtl);

    cudaStreamWaitEvent(0, evProb[t], 0);
    clear_epi(a);
    a.nseg = 1; a.bstrideB = (long)Dd * Nn;
    seg(a, 0, prh, prl, Nn, vth, vtl, Nn);
    a.Oh = mgh; a.Ol = mgl;
    runS(a, 0);

    if (t == 0) {
      clear_epi(a);
      a.nseg = 1;
      seg(a, 0, mgh, mgl, Dd, wmuh + Dd, wmul2 + Dd, 2 * Dd);
      a.rowv = ent_mask; a.colv = ic_mu; a.bias = b_mu;
      a.Oh = xch; a.Ol = xcl; a.rowmul = ent_mask;
      runS(a, 0);
    } else {
      clear_epi(a);
      a.nseg = 2;
      seg(a, 0, xch, xcl, Dd, wmuh, wmul2, 2 * Dd);
      seg(a, 1, mgh, mgl, Dd, wmuh + Dd, wmul2 + Dd, 2 * Dd);
      a.bias = b_mu;
      if (t < Tt - 1) {
        a.Oh = xch; a.Ol = xcl; a.rowmul = ent_mask;
      } else {
        a.Oh = xth; a.Ol = xtl;
      }
      runS(a, 0);
    }
  }

  cudaStreamWaitEvent(0, evOutE, 0);
  clear_epi(a);
  a.nseg = 1;
  seg(a, 0, xth, xtl, Dd, wcbh + Dd, wcbl + Dd, 2 * Dd);
  a.C = out; a.Cadd = out; a.bias = b_cb;
  runS(a, 0);
}